// round 13
// baseline (speedup 1.0000x reference)
#include <cuda_runtime.h>
#include <cuda_bf16.h>
#include <math.h>
#include <stdint.h>

// Problem constants: B=16, N=64, S=4, H=W=32, DG=8, K=9, EPS=1e-5.  BS = 64 images.
#define EPSV 1e-5f

// ---------------- scratch ----------------
__device__ float g_t1  [64 * 64  * 1024];
__device__ float g_st1 [4 * 64 * 2];
__device__ float g_t2  [64 * 128 * 1024];
__device__ float g_off1[64 * 144 * 1024];
__device__ __nv_bfloat16 g_P1h[(size_t)64 * 1024 * 1152];   // deform1 patches
__device__ __nv_bfloat16 g_P1l[(size_t)64 * 1024 * 1152];
__device__ float g_t3  [64 * 128 * 1024];
__device__ float g_st2 [4 * 128 * 2];
__device__ float g_t4  [64 * 128 * 256];
__device__ float g_off2[64 * 144 * 256];
__device__ __nv_bfloat16 g_P2h[(size_t)64 * 256 * 1152];    // deform2 patches
__device__ __nv_bfloat16 g_P2l[(size_t)64 * 256 * 1152];
__device__ float g_t5  [64 * 256 * 256];
__device__ float g_st3 [4 * 256 * 2];
__device__ float g_t6  [64 * 256 * 64];
__device__ __nv_bfloat16 g_w1h [128 * 1152], g_w1l [128 * 1152];   // wd1
__device__ __nv_bfloat16 g_w2h [256 * 1152], g_w2l [256 * 1152];   // wd2
__device__ __nv_bfloat16 g_wc2h[128 * 576],  g_wc2l[128 * 576];    // w2 (conv2)
__device__ __nv_bfloat16 g_wo1h[144 * 1152], g_wo1l[144 * 1152];   // wo1
__device__ __nv_bfloat16 g_wo2h[144 * 1152], g_wo2l[144 * 1152];   // wo2

// ---------------- helpers ----------------
__device__ __forceinline__ uint32_t smem_u32(const void* p) {
    uint32_t a;
    asm("{ .reg .u64 t; cvta.to.shared.u64 t, %1; cvt.u32.u64 %0, t; }" : "=r"(a) : "l"(p));
    return a;
}
__device__ __forceinline__ void ldsm4(uint32_t* r, uint32_t addr) {
    asm volatile("ldmatrix.sync.aligned.m8n8.x4.shared.b16 {%0,%1,%2,%3}, [%4];"
                 : "=r"(r[0]), "=r"(r[1]), "=r"(r[2]), "=r"(r[3]) : "r"(addr));
}
__device__ __forceinline__ void mma16816(float* c, const uint32_t* a, uint32_t b0, uint32_t b1) {
    asm volatile("mma.sync.aligned.m16n8k16.row.col.f32.bf16.bf16.f32 "
                 "{%0,%1,%2,%3}, {%4,%5,%6,%7}, {%8,%9}, {%0,%1,%2,%3};"
                 : "+f"(c[0]), "+f"(c[1]), "+f"(c[2]), "+f"(c[3])
                 : "r"(a[0]), "r"(a[1]), "r"(a[2]), "r"(a[3]), "r"(b0), "r"(b1));
}
__device__ __forceinline__ uint32_t split_pack(float v) {
    __nv_bfloat16 h = __float2bfloat16(v);
    float r = v - __bfloat162float(h);
    __nv_bfloat16 l = __float2bfloat16(r);
    return (uint32_t)__bfloat16_as_ushort(h) | ((uint32_t)__bfloat16_as_ushort(l) << 16);
}

// ---------------- f32x2 helpers (conv1 only) ----------------
__device__ __forceinline__ unsigned long long pack2(float lo, float hi) {
    unsigned long long r;
    asm("mov.b64 %0, {%1, %2};" : "=l"(r) : "f"(lo), "f"(hi));
    return r;
}
__device__ __forceinline__ void unpack2(unsigned long long v, float& lo, float& hi) {
    asm("mov.b64 {%0, %1}, %2;" : "=f"(lo), "=f"(hi) : "l"(v));
}
__device__ __forceinline__ void ffma2(unsigned long long& d,
                                      unsigned long long a, unsigned long long b) {
    asm("fma.rn.f32x2 %0, %1, %2, %0;" : "+l"(d) : "l"(a), "l"(b));
}

// ---------------- all weight bf16 splits in one launch ----------------
__global__ void wconv_all(const float* wd1, const float* wd2, const float* w2,
                          const float* wo1, const float* wo2) {
    int i = blockIdx.x * 256 + threadIdx.x;
    const float* src; __nv_bfloat16 *hi, *lo; int base;
    if      (i < 147456)  { src = wd1; hi = g_w1h;  lo = g_w1l;  base = 0; }
    else if (i < 442368)  { src = wd2; hi = g_w2h;  lo = g_w2l;  base = 147456; }
    else if (i < 516096)  { src = w2;  hi = g_wc2h; lo = g_wc2l; base = 442368; }
    else if (i < 681984)  { src = wo1; hi = g_wo1h; lo = g_wo1l; base = 516096; }
    else if (i < 847872)  { src = wo2; hi = g_wo2h; lo = g_wo2l; base = 681984; }
    else return;
    int j = i - base;
    float v = src[j];
    __nv_bfloat16 h = __float2bfloat16(v);
    hi[j] = h;
    lo[j] = __float2bfloat16(v - __bfloat162float(h));
}

// ---------------- direct 3x3 conv (oc-paired f32x2) — conv1 only, reads x in-place ----------------
template<int CIN, int COUT, int HW, int CHUNK, int BLKT, bool RELU>
__global__ void __launch_bounds__(BLKT) conv3x3_v2(
    const float* __restrict__ in, const float* __restrict__ wt,
    const float* __restrict__ bias, float* __restrict__ out)
{
    constexpr int NP    = HW * HW;
    constexpr int P     = NP / BLKT;
    constexpr int PLW   = HW + 2;
    constexpr int PLANE = PLW * PLW;

    __shared__ __align__(16) float  s_in[CHUNK * PLANE];
    __shared__ __align__(16) float2 s_w2[CHUNK * 8 * 9];

    const int bs  = blockIdx.y;
    const int b   = bs >> 2, s = bs & 3;
    const int oc0 = blockIdx.x * 16;
    const int tid = threadIdx.x;

    unsigned long long acc2[8][P];
#pragma unroll
    for (int op = 0; op < 8; op++) {
        unsigned long long bv = pack2(bias[oc0 + 2 * op], bias[oc0 + 2 * op + 1]);
#pragma unroll
        for (int j = 0; j < P; j++) acc2[op][j] = bv;
    }

    for (int cc = 0; cc < CIN; cc += CHUNK) {
        __syncthreads();
        for (int i = tid; i < CHUNK * PLANE; i += BLKT) {
            int ci = i / PLANE, r = i - ci * PLANE;
            int y = r / PLW - 1, x = r % PLW - 1;
            float v = 0.f;
            if (y >= 0 && y < HW && x >= 0 && x < HW)
                v = in[((size_t)(b * CIN + cc + ci) * 4 + s) * NP + y * HW + x];
            s_in[i] = v;
        }
        for (int i = tid; i < CHUNK * 72; i += BLKT) {
            int ci = i / 72, r = i - ci * 72;
            int op = r / 9, t = r - op * 9;
            s_w2[i] = make_float2(
                wt[((size_t)(oc0 + 2 * op    ) * CIN + cc + ci) * 9 + t],
                wt[((size_t)(oc0 + 2 * op + 1) * CIN + cc + ci) * 9 + t]);
        }
        __syncthreads();

#pragma unroll 1
        for (int ci = 0; ci < CHUNK; ci++) {
            unsigned long long nb2[P][9];
#pragma unroll
            for (int j = 0; j < P; j++) {
                int p = tid + j * BLKT;
                const float* base = s_in + ci * PLANE + (p / HW) * PLW + (p % HW);
#pragma unroll
                for (int t = 0; t < 9; t++) {
                    float f = base[(t / 3) * PLW + (t % 3)];
                    nb2[j][t] = pack2(f, f);
                }
            }
#pragma unroll
            for (int op = 0; op < 8; op++) {
                const unsigned long long* wp =
                    (const unsigned long long*)&s_w2[(ci * 8 + op) * 9];
                unsigned long long w[9];
#pragma unroll
                for (int t = 0; t < 9; t++) w[t] = wp[t];
#pragma unroll
                for (int j = 0; j < P; j++)
#pragma unroll
                    for (int t = 0; t < 9; t++)
                        ffma2(acc2[op][j], nb2[j][t], w[t]);
            }
        }
    }

    float* ob = out + (size_t)bs * COUT * NP;
#pragma unroll
    for (int op = 0; op < 8; op++)
#pragma unroll
        for (int j = 0; j < P; j++) {
            float lo, hi;
            unpack2(acc2[op][j], lo, hi);
            if (RELU) { lo = fmaxf(lo, 0.f); hi = fmaxf(hi, 0.f); }
            int p = tid + j * BLKT;
            ob[(size_t)(oc0 + 2 * op    ) * NP + p] = lo;
            ob[(size_t)(oc0 + 2 * op + 1) * NP + p] = hi;
        }
}

// ---------------- BN stats per (s, c) ----------------
template<int C, int NP, bool RELU, bool GPS>
__global__ void __launch_bounds__(256) bnstats_kernel(
    const float* __restrict__ in, const float* __restrict__ g,
    const float* __restrict__ be, float* __restrict__ stats)
{
    const int sc_ = blockIdx.x;
    const int s = sc_ / C, c = sc_ % C;
    double sum = 0.0, sq = 0.0;
    for (int i = threadIdx.x; i < 16 * NP; i += 256) {
        int b = i / NP, p = i - b * NP;
        float v = in[((size_t)(b * 4 + s) * C + c) * NP + p];
        if (RELU) v = fmaxf(v, 0.f);
        sum += v;
        sq  += (double)v * v;
    }
    __shared__ double rs[256], rq[256];
    rs[threadIdx.x] = sum; rq[threadIdx.x] = sq;
    __syncthreads();
    for (int st = 128; st > 0; st >>= 1) {
        if (threadIdx.x < st) {
            rs[threadIdx.x] += rs[threadIdx.x + st];
            rq[threadIdx.x] += rq[threadIdx.x + st];
        }
        __syncthreads();
    }
    if (threadIdx.x == 0) {
        double cnt = 16.0 * NP;
        double m   = rs[0] / cnt;
        double var = rq[0] / cnt - m * m;
        float gg = GPS ? g[s]  : g[c];
        float bb = GPS ? be[s] : be[c];
        float scl = gg / sqrtf((float)var + EPSV);
        stats[sc_ * 2]     = scl;
        stats[sc_ * 2 + 1] = bb - (float)m * scl;
    }
}

// ---------------- BN apply + 2x2 maxpool ----------------
template<int C, int HW, bool RELU, bool EMB>
__global__ void __launch_bounds__(256) bnpool_kernel(
    const float* __restrict__ in, const float* __restrict__ stats,
    float* __restrict__ out, float* __restrict__ emb)
{
    constexpr int HO = HW / 2, NPO = HO * HO, NPI = HW * HW;
    int idx = blockIdx.x * 256 + threadIdx.x;
    if (idx >= 64 * C * NPO) return;
    int p    = idx % NPO;
    int rest = idx / NPO;
    int c  = rest % C;
    int bs = rest / C;
    int s  = bs & 3;
    int oy = p / HO, ox = p % HO;
    float scl = stats[(s * C + c) * 2];
    float sh  = stats[(s * C + c) * 2 + 1];
    const float* ib = in + ((size_t)bs * C + c) * NPI + (2 * oy) * HW + 2 * ox;
    float m = -INFINITY;
#pragma unroll
    for (int dy = 0; dy < 2; dy++)
#pragma unroll
        for (int dx = 0; dx < 2; dx++) {
            float v = ib[dy * HW + dx];
            if (RELU) v = fmaxf(v, 0.f);
            v = fmaf(v, scl, sh);
            m = fmaxf(m, v);
        }
    out[idx] = m;
    if (EMB) {
        int b = bs >> 2;
        emb[(((size_t)b * C + c) * 4 + s) * NPO + p] = m;
    }
}

// ---------------- fused implicit-GEMM conv (pipelined, double-buffered) ----------------
// out[MROWS x NPIX] = W[MROWS x CIN*9] @ patches(in)^T + bias
template<int MROWS, int WROWS, int MA, int CIN, int HW, int NPIX, bool NORM>
__global__ void __launch_bounds__(WROWS * 128) cgemm(
    const __nv_bfloat16* __restrict__ Whi, const __nv_bfloat16* __restrict__ Wlo,
    const float* __restrict__ bias, const float* __restrict__ in,
    const float* __restrict__ stats, float* __restrict__ out)
{
    constexpr int KK      = CIN * 9;
    constexpr int NCH     = KK / 32;
    constexpr int MTILE   = WROWS * MA * 16;
    constexpr int THREADS = WROWS * 128;
    constexpr int STR     = 40;
    constexpr int ASZ     = 2 * MTILE * STR;     // elems per A buffer
    constexpr int BSZ     = 2 * 128 * STR;       // elems per B buffer
    constexpr int TROWS   = 128 / HW;
    constexpr int PADW    = HW + 2;
    constexpr int ROWS    = TROWS + 2;
    constexpr int PLANE   = ROWS * PADW;
    constexpr int NP      = HW * HW;

    extern __shared__ char dsm[];
    uint32_t*      s_img = (uint32_t*)dsm;
    __nv_bfloat16* sA    = (__nv_bfloat16*)(dsm + CIN * PLANE * 4);   // [2 bufs][2 arr][MTILE][STR]
    __nv_bfloat16* sB    = sA + 2 * ASZ;                              // [2 bufs][2 arr][128][STR]

    const int tid  = threadIdx.x;
    const int warp = tid >> 5, lane = tid & 31;
    const int wm = warp >> 2, wn = warp & 3;
    const int bs = blockIdx.y;
    const int s  = bs & 3;
    const int nt = blockIdx.x;
    const int n0 = nt * 128, y0 = nt * TROWS;
    const int g  = lane >> 2, tg = lane & 3;

    // stage padded image region, packed (hi|lo)
    const float* inb = in + (size_t)bs * CIN * NP;
    for (int i = tid; i < CIN * PLANE; i += THREADS) {
        int ci = i / PLANE, r = i - ci * PLANE;
        int ry = r / PADW, rx = r - ry * PADW;
        int gy = y0 + ry - 1, gx = rx - 1;
        uint32_t pk = 0;
        if (gy >= 0 && gy < HW && gx >= 0 && gx < HW) {
            float v = inb[(size_t)ci * NP + gy * HW + gx];
            if (NORM)
                v = fmaf(v, stats[(s * CIN + ci) * 2], stats[(s * CIN + ci) * 2 + 1]);
            pk = split_pack(v);
        }
        s_img[i] = pk;
    }

    float acc[MA][4][4] = {};

    const uint32_t baseA[2] = { smem_u32(sA), smem_u32(sA + ASZ) };
    const uint32_t baseB[2] = { smem_u32(sB), smem_u32(sB + BSZ) };
    const int arowA = wm * (MA * 16) + (lane & 15);
    const int acolA = (lane >> 4) * 8;
    const int browB = wn * 32 + (lane & 7) + ((lane >> 4) & 1) * 8;
    const int bcolB = ((lane >> 3) & 1) * 8;

    // chunk stager: A weights from gmem, B tile built from staged image
    auto stage_chunk = [&](int kc, int buf) {
        __nv_bfloat16* pA = sA + buf * ASZ;
        __nv_bfloat16* pB = sB + buf * BSZ;
        for (int i = tid; i < MTILE * 8; i += THREADS) {
            int arr = i / (MTILE * 4);
            int r   = (i >> 2) % MTILE;
            int seg = i & 3;
            const __nv_bfloat16* src =
                (arr ? Wlo : Whi) + (size_t)r * KK + kc * 32 + seg * 8;
            *(uint4*)&pA[(arr * MTILE + r) * STR + seg * 8] = *(const uint4*)src;
        }
        for (int i = tid; i < 4096; i += THREADS) {
            int n = i >> 5, kloc = i & 31;
            int k  = kc * 32 + kloc;
            int ci = k / 9, tap = k - ci * 9;
            int dy = tap / 3, dx = tap - dy * 3;
            int yl = n / HW, xl = n - yl * HW;
            uint32_t pk = s_img[ci * PLANE + (yl + dy) * PADW + (xl + dx)];
            ((uint16_t*)pB)[n * STR + kloc]         = (uint16_t)(pk & 0xFFFF);
            ((uint16_t*)pB)[(128 + n) * STR + kloc] = (uint16_t)(pk >> 16);
        }
    };

    __syncthreads();          // s_img ready
    stage_chunk(0, 0);
    __syncthreads();

    for (int kc = 0; kc < NCH; kc++) {
        const int buf = kc & 1;
        const uint32_t bA0 = baseA[buf], bA1 = baseA[buf] + MTILE * STR * 2;
        const uint32_t bB0 = baseB[buf], bB1 = baseB[buf] + 128 * STR * 2;
#pragma unroll
        for (int ks = 0; ks < 2; ks++) {
            uint32_t a[2][MA][4];
#pragma unroll
            for (int ma = 0; ma < MA; ma++) {
                ldsm4(a[0][ma], bA0 + (uint32_t)((arowA + ma * 16) * STR + ks * 16 + acolA) * 2);
                ldsm4(a[1][ma], bA1 + (uint32_t)((arowA + ma * 16) * STR + ks * 16 + acolA) * 2);
            }
            uint32_t b[2][2][4];
#pragma unroll
            for (int np = 0; np < 2; np++) {
                ldsm4(b[0][np], bB0 + (uint32_t)((browB + np * 16) * STR + ks * 16 + bcolB) * 2);
                ldsm4(b[1][np], bB1 + (uint32_t)((browB + np * 16) * STR + ks * 16 + bcolB) * 2);
            }
#pragma unroll
            for (int ma = 0; ma < MA; ma++)
#pragma unroll
                for (int na = 0; na < 4; na++) {
                    int np = na >> 1, sub = na & 1;
                    uint32_t bh0 = b[0][np][sub * 2], bh1 = b[0][np][sub * 2 + 1];
                    uint32_t bl0 = b[1][np][sub * 2], bl1 = b[1][np][sub * 2 + 1];
                    mma16816(acc[ma][na], a[0][ma], bh0, bh1);
                    mma16816(acc[ma][na], a[0][ma], bl0, bl1);
                    mma16816(acc[ma][na], a[1][ma], bh0, bh1);
                }
        }
        if (kc + 1 < NCH) stage_chunk(kc + 1, buf ^ 1);
        __syncthreads();
    }

    // epilogue
#pragma unroll
    for (int ma = 0; ma < MA; ma++) {
        int mA = wm * (MA * 16) + ma * 16 + g;
        int mB = mA + 8;
        float bvA = bias[mA], bvB = bias[mB];
        float* orA = out + ((size_t)bs * MROWS + mA) * NPIX + n0 + wn * 32;
        float* orB = out + ((size_t)bs * MROWS + mB) * NPIX + n0 + wn * 32;
#pragma unroll
        for (int na = 0; na < 4; na++) {
            int nc = na * 8 + 2 * tg;
            *(float2*)(orA + nc) = make_float2(acc[ma][na][0] + bvA, acc[ma][na][1] + bvA);
            *(float2*)(orB + nc) = make_float2(acc[ma][na][2] + bvB, acc[ma][na][3] + bvB);
        }
    }
}

// ---------------- deformable sampling -> K-major bf16 hi/lo patches ----------------
template<int HW>
__global__ void __launch_bounds__(256) dsample_tc(
    const float* __restrict__ in, const float* __restrict__ off,
    __nv_bfloat16* __restrict__ Phi, __nv_bfloat16* __restrict__ Plo)
{
    constexpr int NP = HW * HW;
    constexpr int NCHK = NP / 256;
    extern __shared__ float sdyn[];
    float* s_img = sdyn;
    uint32_t* s_tr = (uint32_t*)(sdyn + 16 * NP);
    const int g  = blockIdx.x;
    const int bs = blockIdx.y;
    const int tid = threadIdx.x;
    const float* inb = in + ((size_t)bs * 128 + g * 16) * NP;
    for (int i = tid; i < 16 * NP; i += 256) s_img[i] = inb[i];
    __syncthreads();
    const float* offb = off + ((size_t)bs * 144 + g * 18) * NP;
    uint32_t* Ph32 = (uint32_t*)Phi;
    uint32_t* Pl32 = (uint32_t*)Plo;
    const size_t imgbase = (size_t)bs * NP * 1152;

    for (int chunk = 0; chunk < NCHK; chunk++) {
        int p = chunk * 256 + tid;
        int y = p / HW, x = p % HW;
#pragma unroll
        for (int k = 0; k < 9; k++) {
            float py = (float)(y + (k / 3) - 1) + offb[(size_t)(2 * k) * NP + p];
            float px = (float)(x + (k % 3) - 1) + offb[(size_t)(2 * k + 1) * NP + p];
            float fy = floorf(py), fx = floorf(px);
            float ly = py - fy, lx = px - fx;
            int y0 = (int)fy, x0 = (int)fx;
            int y1 = y0 + 1,  x1 = x0 + 1;
            float vy0 = (y0 >= 0 && y0 < HW) ? 1.f : 0.f;
            float vy1 = (y1 >= 0 && y1 < HW) ? 1.f : 0.f;
            float vx0 = (x0 >= 0 && x0 < HW) ? 1.f : 0.f;
            float vx1 = (x1 >= 0 && x1 < HW) ? 1.f : 0.f;
            int yc0 = min(max(y0, 0), HW - 1), yc1 = min(max(y1, 0), HW - 1);
            int xc0 = min(max(x0, 0), HW - 1), xc1 = min(max(x1, 0), HW - 1);
            float w00 = (1.f - ly) * (1.f - lx) * vy0 * vx0;
            float w01 = (1.f - ly) * lx         * vy0 * vx1;
            float w10 = ly         * (1.f - lx) * vy1 * vx0;
            float w11 = ly         * lx         * vy1 * vx1;
            int i00 = yc0 * HW + xc0, i01 = yc0 * HW + xc1;
            int i10 = yc1 * HW + xc0, i11 = yc1 * HW + xc1;
#pragma unroll
            for (int cp = 0; cp < 16; cp++) {
                const float* pl = s_img + cp * NP;
                float v = w00 * pl[i00] + w01 * pl[i01] + w10 * pl[i10] + w11 * pl[i11];
                s_tr[tid * 144 + cp * 9 + k] = split_pack(v);
            }
        }
        __syncthreads();
        for (int idx = tid; idx < 256 * 72; idx += 256) {
            int row = idx / 72, j = idx % 72;
            uint32_t a  = s_tr[row * 144 + 2 * j];
            uint32_t b2 = s_tr[row * 144 + 2 * j + 1];
            uint32_t hp = __byte_perm(a, b2, 0x5410);
            uint32_t lp = __byte_perm(a, b2, 0x7632);
            size_t o = imgbase + (size_t)(chunk * 256 + row) * 1152 + g * 144 + 2 * j;
            Ph32[o >> 1] = hp;
            Pl32[o >> 1] = lp;
        }
        __syncthreads();
    }
}

// ---------------- warp-MMA bf16-split GEMM (deform; pipelined, double-buffered) ----------------
template<int MROWS, int KK, int NPIX>
__global__ void __launch_bounds__(256) gemm_mma(
    const __nv_bfloat16* __restrict__ Whi, const __nv_bfloat16* __restrict__ Wlo,
    const float* __restrict__ bias,
    const __nv_bfloat16* __restrict__ Phi, const __nv_bfloat16* __restrict__ Plo,
    float* __restrict__ out)
{
    constexpr int MT  = MROWS / 128;
    constexpr int NCH = KK / 32;
    constexpr int STR = 40;
    constexpr int HSZ = 2 * 128 * STR;        // elems per (A or B) buffer

    extern __shared__ char dsm[];
    __nv_bfloat16* sA = (__nv_bfloat16*)dsm;  // [2 bufs][2 arr][128][STR]
    __nv_bfloat16* sB = sA + 2 * HSZ;

    const int tid  = threadIdx.x;
    const int warp = tid >> 5, lane = tid & 31;
    const int wm = warp >> 2, wn = warp & 3;
    const int bs = blockIdx.y;
    const int mt = blockIdx.x % MT, nt = blockIdx.x / MT;
    const int m0 = mt * 128, n0 = nt * 128;
    const int g  = lane >> 2, tg = lane & 3;

    float acc[4][4][4] = {};

    const uint32_t baseA[2] = { smem_u32(sA), smem_u32(sA + HSZ) };
    const uint32_t baseB[2] = { smem_u32(sB), smem_u32(sB + HSZ) };
    const int arowA = wm * 64 + (lane & 15);
    const int acolA = (lane >> 4) * 8;
    const int browB = wn * 32 + (lane & 7) + ((lane >> 4) & 1) * 8;
    const int bcolB = ((lane >> 3) & 1) * 8;

    const size_t prow = (size_t)bs * NPIX + n0;

    auto stage_chunk = [&](int kc, int buf) {
        __nv_bfloat16* pA = sA + buf * HSZ;
        __nv_bfloat16* pB = sB + buf * HSZ;
        for (int i = tid; i < 2048; i += 256) {
            int half = i >> 10;
            int arr  = (i >> 9) & 1;
            int r    = (i >> 2) & 127;
            int seg  = i & 3;
            if (half == 0) {
                const __nv_bfloat16* src =
                    (arr ? Wlo : Whi) + (size_t)(m0 + r) * KK + kc * 32 + seg * 8;
                *(uint4*)&pA[(arr * 128 + r) * STR + seg * 8] = *(const uint4*)src;
            } else {
                const __nv_bfloat16* src =
                    (arr ? Plo : Phi) + (prow + r) * KK + kc * 32 + seg * 8;
                *(uint4*)&pB[(arr * 128 + r) * STR + seg * 8] = *(const uint4*)src;
            }
        }
    };

    stage_chunk(0, 0);
    __syncthreads();

    for (int kc = 0; kc < NCH; kc++) {
        const int buf = kc & 1;
        const uint32_t bA0 = baseA[buf], bA1 = baseA[buf] + 128 * STR * 2;
        const uint32_t bB0 = baseB[buf], bB1 = baseB[buf] + 128 * STR * 2;
#pragma unroll
        for (int ks = 0; ks < 2; ks++) {
            uint32_t a[2][4][4];
#pragma unroll
            for (int ma = 0; ma < 4; ma++) {
                ldsm4(a[0][ma], bA0 + (uint32_t)((arowA + ma * 16) * STR + ks * 16 + acolA) * 2);
                ldsm4(a[1][ma], bA1 + (uint32_t)((arowA + ma * 16) * STR + ks * 16 + acolA) * 2);
            }
            uint32_t b[2][2][4];
#pragma unroll
            for (int np = 0; np < 2; np++) {
                ldsm4(b[0][np], bB0 + (uint32_t)((browB + np * 16) * STR + ks * 16 + bcolB) * 2);
                ldsm4(b[1][np], bB1 + (uint32_t)((browB + np * 16) * STR + ks * 16 + bcolB) * 2);
            }
#pragma unroll
            for (int ma = 0; ma < 4; ma++)
#pragma unroll
                for (int na = 0; na < 4; na++) {
                    int np = na >> 1, sub = na & 1;
                    uint32_t bh0 = b[0][np][sub * 2], bh1 = b[0][np][sub * 2 + 1];
                    uint32_t bl0 = b[1][np][sub * 2], bl1 = b[1][np][sub * 2 + 1];
                    mma16816(acc[ma][na], a[0][ma], bh0, bh1);
                    mma16816(acc[ma][na], a[0][ma], bl0, bl1);
                    mma16816(acc[ma][na], a[1][ma], bh0, bh1);
                }
        }
        if (kc + 1 < NCH) stage_chunk(kc + 1, buf ^ 1);
        __syncthreads();
    }

#pragma unroll
    for (int ma = 0; ma < 4; ma++) {
        int mA = m0 + wm * 64 + ma * 16 + g;
        int mB = mA + 8;
        float bvA = bias[mA], bvB = bias[mB];
        float* orA = out + ((size_t)bs * MROWS + mA) * NPIX + n0 + wn * 32;
        float* orB = out + ((size_t)bs * MROWS + mB) * NPIX + n0 + wn * 32;
#pragma unroll
        for (int na = 0; na < 4; na++) {
            int nc = na * 8 + 2 * tg;
            *(float2*)(orA + nc) = make_float2(acc[ma][na][0] + bvA, acc[ma][na][1] + bvA);
            *(float2*)(orB + nc) = make_float2(acc[ma][na][2] + bvB, acc[ma][na][3] + bvB);
        }
    }
}

// ---------------- strength (relu of max over s) + FC -> logits ----------------
__global__ void __launch_bounds__(256) fc_kernel(
    const float* __restrict__ t6, const float* __restrict__ wfc,
    const float* __restrict__ bfc, float* __restrict__ out)
{
    const int b = blockIdx.x;
    float acc[10];
#pragma unroll
    for (int j = 0; j < 10; j++) acc[j] = 0.f;
    const float* tb0 = t6 + (size_t)b * 4 * 16384;
    for (int i = threadIdx.x; i < 16384; i += 256) {
        float m = tb0[i];
        m = fmaxf(m, tb0[i + 16384]);
        m = fmaxf(m, tb0[i + 2 * 16384]);
        m = fmaxf(m, tb0[i + 3 * 16384]);
        m = fmaxf(m, 0.f);
#pragma unroll
        for (int j = 0; j < 10; j++)
            acc[j] = fmaf(m, wfc[(size_t)j * 16384 + i], acc[j]);
    }
    __shared__ float red[256];
    for (int j = 0; j < 10; j++) {
        red[threadIdx.x] = acc[j];
        __syncthreads();
        for (int st = 128; st > 0; st >>= 1) {
            if (threadIdx.x < st) red[threadIdx.x] += red[threadIdx.x + st];
            __syncthreads();
        }
        if (threadIdx.x == 0) out[b * 10 + j] = red[0] + bfc[j];
        __syncthreads();
    }
}

// ---------------- launch ----------------
extern "C" void kernel_launch(void* const* d_in, const int* in_sizes, int n_in,
                              void* d_out, int out_size) {
    const float* x   = (const float*)d_in[0];
    const float* w1  = (const float*)d_in[1];
    const float* b1  = (const float*)d_in[2];
    const float* g1  = (const float*)d_in[3];
    const float* be1 = (const float*)d_in[4];
    const float* w2  = (const float*)d_in[5];
    const float* b2  = (const float*)d_in[6];
    const float* wo1 = (const float*)d_in[7];
    const float* bo1 = (const float*)d_in[8];
    const float* wd1 = (const float*)d_in[9];
    const float* bd1 = (const float*)d_in[10];
    const float* g2  = (const float*)d_in[11];
    const float* be2 = (const float*)d_in[12];
    const float* wo2 = (const float*)d_in[13];
    const float* bo2 = (const float*)d_in[14];
    const float* wd2 = (const float*)d_in[15];
    const float* bd2 = (const float*)d_in[16];
    const float* g3  = (const float*)d_in[17];
    const float* be3 = (const float*)d_in[18];
    const float* wfc = (const float*)d_in[19];
    const float* bfc = (const float*)d_in[20];
    float* out = (float*)d_out;

    float *t1, *st1, *t2, *off1, *t3, *st2, *t4, *off2, *t5, *st3, *t6;
    __nv_bfloat16 *P1h, *P1l, *P2h, *P2l;
    __nv_bfloat16 *w1h, *w1l, *w2h, *w2l, *wc2h, *wc2l, *wo1h, *wo1l, *wo2h, *wo2l;
    cudaGetSymbolAddress((void**)&t1,   g_t1);
    cudaGetSymbolAddress((void**)&st1,  g_st1);
    cudaGetSymbolAddress((void**)&t2,   g_t2);
    cudaGetSymbolAddress((void**)&off1, g_off1);
    cudaGetSymbolAddress((void**)&P1h,  g_P1h);
    cudaGetSymbolAddress((void**)&P1l,  g_P1l);
    cudaGetSymbolAddress((void**)&t3,   g_t3);
    cudaGetSymbolAddress((void**)&st2,  g_st2);
    cudaGetSymbolAddress((void**)&t4,   g_t4);
    cudaGetSymbolAddress((void**)&off2, g_off2);
    cudaGetSymbolAddress((void**)&P2h,  g_P2h);
    cudaGetSymbolAddress((void**)&P2l,  g_P2l);
    cudaGetSymbolAddress((void**)&t5,   g_t5);
    cudaGetSymbolAddress((void**)&st3,  g_st3);
    cudaGetSymbolAddress((void**)&t6,   g_t6);
    cudaGetSymbolAddress((void**)&w1h,  g_w1h);
    cudaGetSymbolAddress((void**)&w1l,  g_w1l);
    cudaGetSymbolAddress((void**)&w2h,  g_w2h);
    cudaGetSymbolAddress((void**)&w2l,  g_w2l);
    cudaGetSymbolAddress((void**)&wc2h, g_wc2h);
    cudaGetSymbolAddress((void**)&wc2l, g_wc2l);
    cudaGetSymbolAddress((void**)&wo1h, g_wo1h);
    cudaGetSymbolAddress((void**)&wo1l, g_wo1l);
    cudaGetSymbolAddress((void**)&wo2h, g_wo2h);
    cudaGetSymbolAddress((void**)&wo2l, g_wo2l);

    cudaFuncSetAttribute(dsample_tc<32>, cudaFuncAttributeMaxDynamicSharedMemorySize, 212992);
    cudaFuncSetAttribute(dsample_tc<16>, cudaFuncAttributeMaxDynamicSharedMemorySize, 163840);
    // cgemm smem: s_img + 2x A bufs + 2x B bufs
    cudaFuncSetAttribute((const void*)cgemm<128, 2, 4, 64, 32, 1024, true>,
                         cudaFuncAttributeMaxDynamicSharedMemorySize, 52224 + 40960 + 40960);
    cudaFuncSetAttribute((const void*)cgemm<144, 3, 3, 128, 32, 1024, false>,
                         cudaFuncAttributeMaxDynamicSharedMemorySize, 104448 + 46080 + 40960);
    cudaFuncSetAttribute((const void*)cgemm<144, 3, 3, 128, 16, 256, false>,
                         cudaFuncAttributeMaxDynamicSharedMemorySize, 92160 + 46080 + 40960);
    // gemm_mma smem: 2 bufs x (A + B)
    cudaFuncSetAttribute((const void*)gemm_mma<128, 1152, 1024>,
                         cudaFuncAttributeMaxDynamicSharedMemorySize, 81920);
    cudaFuncSetAttribute((const void*)gemm_mma<256, 1152, 256>,
                         cudaFuncAttributeMaxDynamicSharedMemorySize, 81920);

    // 1: all weight splits (one launch)
    wconv_all<<<(847872 + 255) / 256, 256>>>(wd1, wd2, w2, wo1, wo2);
    // 2: conv1 + relu (FFMA2, reads x in packed layout directly)
    conv3x3_v2<3, 64, 32, 3, 512, true><<<dim3(4, 64), 512>>>(x, w1, b1, t1);
    // 3: BN1 stats
    bnstats_kernel<64, 1024, false, false><<<256, 256>>>(t1, g1, be1, st1);
    // 4: conv2 fused implicit-GEMM (BN1 folded at staging)  <- profiled launch
    cgemm<128, 2, 4, 64, 32, 1024, true><<<dim3(8, 64), 256, 134144>>>(
        wc2h, wc2l, b2, t1, st1, t2);
    // 5: offset conv 1 fused
    cgemm<144, 3, 3, 128, 32, 1024, false><<<dim3(8, 64), 384, 191488>>>(
        wo1h, wo1l, bo1, t2, nullptr, off1);
    // deform 1: sample + GEMM
    dsample_tc<32><<<dim3(8, 64), 256, 212992>>>(t2, off1, P1h, P1l);
    gemm_mma<128, 1152, 1024><<<dim3(8, 64), 256, 81920>>>(w1h, w1l, bd1, P1h, P1l, t3);
    // relu + BN2 + maxpool
    bnstats_kernel<128, 1024, true, true><<<512, 256>>>(t3, g2, be2, st2);
    bnpool_kernel<128, 32, true, false><<<(64 * 128 * 256) / 256, 256>>>(t3, st2, t4, nullptr);
    // offset conv 2 fused
    cgemm<144, 3, 3, 128, 16, 256, false><<<dim3(2, 64), 384, 179200>>>(
        wo2h, wo2l, bo2, t4, nullptr, off2);
    // deform 2: sample + GEMM
    dsample_tc<16><<<dim3(8, 64), 256, 163840>>>(t4, off2, P2h, P2l);
    gemm_mma<256, 1152, 256><<<dim3(4, 64), 256, 81920>>>(w2h, w2l, bd2, P2h, P2l, t5);
    // BN3 + maxpool, write embedding to out[160:]
    bnstats_kernel<256, 256, false, true><<<1024, 256>>>(t5, g3, be3, st3);
    bnpool_kernel<256, 16, false, true><<<(64 * 256 * 64) / 256, 256>>>(t5, st3, t6, out + 160);
    // logits to out[0:160]
    fc_kernel<<<16, 256>>>(t6, wfc, bfc, out);
}

// round 14
// speedup vs baseline: 1.6404x; 1.6404x over previous
#include <cuda_runtime.h>
#include <cuda_bf16.h>
#include <math.h>
#include <stdint.h>

// Problem constants: B=16, N=64, S=4, H=W=32, DG=8, K=9, EPS=1e-5.  BS = 64 images.
#define EPSV 1e-5f

// ---------------- scratch ----------------
__device__ float g_t1  [64 * 64  * 1024];
__device__ float g_st1 [4 * 64 * 2];
__device__ float g_t2  [64 * 128 * 1024];
__device__ float g_off1[64 * 144 * 1024];
__device__ __nv_bfloat16 g_P1h[(size_t)64 * 1024 * 1152];   // deform1 patches
__device__ __nv_bfloat16 g_P1l[(size_t)64 * 1024 * 1152];
__device__ float g_t3  [64 * 128 * 1024];
__device__ float g_st2 [4 * 128 * 2];
__device__ float g_t4  [64 * 128 * 256];
__device__ float g_off2[64 * 144 * 256];
__device__ __nv_bfloat16 g_P2h[(size_t)64 * 256 * 1152];    // deform2 patches
__device__ __nv_bfloat16 g_P2l[(size_t)64 * 256 * 1152];
__device__ float g_t5  [64 * 256 * 256];
__device__ float g_st3 [4 * 256 * 2];
__device__ float g_t6  [64 * 256 * 64];
__device__ __nv_bfloat16 g_w1h [128 * 1152], g_w1l [128 * 1152];   // wd1
__device__ __nv_bfloat16 g_w2h [256 * 1152], g_w2l [256 * 1152];   // wd2
__device__ __nv_bfloat16 g_wc2h[128 * 576],  g_wc2l[128 * 576];    // w2 (conv2)
__device__ __nv_bfloat16 g_wo1h[144 * 1152], g_wo1l[144 * 1152];   // wo1
__device__ __nv_bfloat16 g_wo2h[144 * 1152], g_wo2l[144 * 1152];   // wo2

// ---------------- helpers ----------------
__device__ __forceinline__ uint32_t smem_u32(const void* p) {
    uint32_t a;
    asm("{ .reg .u64 t; cvta.to.shared.u64 t, %1; cvt.u32.u64 %0, t; }" : "=r"(a) : "l"(p));
    return a;
}
__device__ __forceinline__ void ldsm4(uint32_t* r, uint32_t addr) {
    asm volatile("ldmatrix.sync.aligned.m8n8.x4.shared.b16 {%0,%1,%2,%3}, [%4];"
                 : "=r"(r[0]), "=r"(r[1]), "=r"(r[2]), "=r"(r[3]) : "r"(addr));
}
__device__ __forceinline__ void mma16816(float* c, const uint32_t* a, uint32_t b0, uint32_t b1) {
    asm volatile("mma.sync.aligned.m16n8k16.row.col.f32.bf16.bf16.f32 "
                 "{%0,%1,%2,%3}, {%4,%5,%6,%7}, {%8,%9}, {%0,%1,%2,%3};"
                 : "+f"(c[0]), "+f"(c[1]), "+f"(c[2]), "+f"(c[3])
                 : "r"(a[0]), "r"(a[1]), "r"(a[2]), "r"(a[3]), "r"(b0), "r"(b1));
}
__device__ __forceinline__ uint32_t split_pack(float v) {
    __nv_bfloat16 h = __float2bfloat16(v);
    float r = v - __bfloat162float(h);
    __nv_bfloat16 l = __float2bfloat16(r);
    return (uint32_t)__bfloat16_as_ushort(h) | ((uint32_t)__bfloat16_as_ushort(l) << 16);
}

// ---------------- f32x2 helpers (conv1 only) ----------------
__device__ __forceinline__ unsigned long long pack2(float lo, float hi) {
    unsigned long long r;
    asm("mov.b64 %0, {%1, %2};" : "=l"(r) : "f"(lo), "f"(hi));
    return r;
}
__device__ __forceinline__ void unpack2(unsigned long long v, float& lo, float& hi) {
    asm("mov.b64 {%0, %1}, %2;" : "=f"(lo), "=f"(hi) : "l"(v));
}
__device__ __forceinline__ void ffma2(unsigned long long& d,
                                      unsigned long long a, unsigned long long b) {
    asm("fma.rn.f32x2 %0, %1, %2, %0;" : "+l"(d) : "l"(a), "l"(b));
}

// ---------------- all weight bf16 splits in one launch ----------------
__global__ void wconv_all(const float* wd1, const float* wd2, const float* w2,
                          const float* wo1, const float* wo2) {
    int i = blockIdx.x * 256 + threadIdx.x;
    const float* src; __nv_bfloat16 *hi, *lo; int base;
    if      (i < 147456)  { src = wd1; hi = g_w1h;  lo = g_w1l;  base = 0; }
    else if (i < 442368)  { src = wd2; hi = g_w2h;  lo = g_w2l;  base = 147456; }
    else if (i < 516096)  { src = w2;  hi = g_wc2h; lo = g_wc2l; base = 442368; }
    else if (i < 681984)  { src = wo1; hi = g_wo1h; lo = g_wo1l; base = 516096; }
    else if (i < 847872)  { src = wo2; hi = g_wo2h; lo = g_wo2l; base = 681984; }
    else return;
    int j = i - base;
    float v = src[j];
    __nv_bfloat16 h = __float2bfloat16(v);
    hi[j] = h;
    lo[j] = __float2bfloat16(v - __bfloat162float(h));
}

// ---------------- direct 3x3 conv (oc-paired f32x2) — conv1 only ----------------
template<int CIN, int COUT, int HW, int CHUNK, int BLKT, bool RELU>
__global__ void __launch_bounds__(BLKT) conv3x3_v2(
    const float* __restrict__ in, const float* __restrict__ wt,
    const float* __restrict__ bias, float* __restrict__ out)
{
    constexpr int NP    = HW * HW;
    constexpr int P     = NP / BLKT;
    constexpr int PLW   = HW + 2;
    constexpr int PLANE = PLW * PLW;

    __shared__ __align__(16) float  s_in[CHUNK * PLANE];
    __shared__ __align__(16) float2 s_w2[CHUNK * 8 * 9];

    const int bs  = blockIdx.y;
    const int b   = bs >> 2, s = bs & 3;
    const int oc0 = blockIdx.x * 16;
    const int tid = threadIdx.x;

    unsigned long long acc2[8][P];
#pragma unroll
    for (int op = 0; op < 8; op++) {
        unsigned long long bv = pack2(bias[oc0 + 2 * op], bias[oc0 + 2 * op + 1]);
#pragma unroll
        for (int j = 0; j < P; j++) acc2[op][j] = bv;
    }

    for (int cc = 0; cc < CIN; cc += CHUNK) {
        __syncthreads();
        for (int i = tid; i < CHUNK * PLANE; i += BLKT) {
            int ci = i / PLANE, r = i - ci * PLANE;
            int y = r / PLW - 1, x = r % PLW - 1;
            float v = 0.f;
            if (y >= 0 && y < HW && x >= 0 && x < HW)
                v = in[((size_t)(b * CIN + cc + ci) * 4 + s) * NP + y * HW + x];
            s_in[i] = v;
        }
        for (int i = tid; i < CHUNK * 72; i += BLKT) {
            int ci = i / 72, r = i - ci * 72;
            int op = r / 9, t = r - op * 9;
            s_w2[i] = make_float2(
                wt[((size_t)(oc0 + 2 * op    ) * CIN + cc + ci) * 9 + t],
                wt[((size_t)(oc0 + 2 * op + 1) * CIN + cc + ci) * 9 + t]);
        }
        __syncthreads();

#pragma unroll 1
        for (int ci = 0; ci < CHUNK; ci++) {
            unsigned long long nb2[P][9];
#pragma unroll
            for (int j = 0; j < P; j++) {
                int p = tid + j * BLKT;
                const float* base = s_in + ci * PLANE + (p / HW) * PLW + (p % HW);
#pragma unroll
                for (int t = 0; t < 9; t++) {
                    float f = base[(t / 3) * PLW + (t % 3)];
                    nb2[j][t] = pack2(f, f);
                }
            }
#pragma unroll
            for (int op = 0; op < 8; op++) {
                const unsigned long long* wp =
                    (const unsigned long long*)&s_w2[(ci * 8 + op) * 9];
                unsigned long long w[9];
#pragma unroll
                for (int t = 0; t < 9; t++) w[t] = wp[t];
#pragma unroll
                for (int j = 0; j < P; j++)
#pragma unroll
                    for (int t = 0; t < 9; t++)
                        ffma2(acc2[op][j], nb2[j][t], w[t]);
            }
        }
    }

    float* ob = out + (size_t)bs * COUT * NP;
#pragma unroll
    for (int op = 0; op < 8; op++)
#pragma unroll
        for (int j = 0; j < P; j++) {
            float lo, hi;
            unpack2(acc2[op][j], lo, hi);
            if (RELU) { lo = fmaxf(lo, 0.f); hi = fmaxf(hi, 0.f); }
            int p = tid + j * BLKT;
            ob[(size_t)(oc0 + 2 * op    ) * NP + p] = lo;
            ob[(size_t)(oc0 + 2 * op + 1) * NP + p] = hi;
        }
}

// ---------------- BN stats per (s, c) ----------------
template<int C, int NP, bool RELU, bool GPS>
__global__ void __launch_bounds__(256) bnstats_kernel(
    const float* __restrict__ in, const float* __restrict__ g,
    const float* __restrict__ be, float* __restrict__ stats)
{
    const int sc_ = blockIdx.x;
    const int s = sc_ / C, c = sc_ % C;
    double sum = 0.0, sq = 0.0;
    for (int i = threadIdx.x; i < 16 * NP; i += 256) {
        int b = i / NP, p = i - b * NP;
        float v = in[((size_t)(b * 4 + s) * C + c) * NP + p];
        if (RELU) v = fmaxf(v, 0.f);
        sum += v;
        sq  += (double)v * v;
    }
    __shared__ double rs[256], rq[256];
    rs[threadIdx.x] = sum; rq[threadIdx.x] = sq;
    __syncthreads();
    for (int st = 128; st > 0; st >>= 1) {
        if (threadIdx.x < st) {
            rs[threadIdx.x] += rs[threadIdx.x + st];
            rq[threadIdx.x] += rq[threadIdx.x + st];
        }
        __syncthreads();
    }
    if (threadIdx.x == 0) {
        double cnt = 16.0 * NP;
        double m   = rs[0] / cnt;
        double var = rq[0] / cnt - m * m;
        float gg = GPS ? g[s]  : g[c];
        float bb = GPS ? be[s] : be[c];
        float scl = gg / sqrtf((float)var + EPSV);
        stats[sc_ * 2]     = scl;
        stats[sc_ * 2 + 1] = bb - (float)m * scl;
    }
}

// ---------------- BN apply + 2x2 maxpool ----------------
template<int C, int HW, bool RELU, bool EMB>
__global__ void __launch_bounds__(256) bnpool_kernel(
    const float* __restrict__ in, const float* __restrict__ stats,
    float* __restrict__ out, float* __restrict__ emb)
{
    constexpr int HO = HW / 2, NPO = HO * HO, NPI = HW * HW;
    int idx = blockIdx.x * 256 + threadIdx.x;
    if (idx >= 64 * C * NPO) return;
    int p    = idx % NPO;
    int rest = idx / NPO;
    int c  = rest % C;
    int bs = rest / C;
    int s  = bs & 3;
    int oy = p / HO, ox = p % HO;
    float scl = stats[(s * C + c) * 2];
    float sh  = stats[(s * C + c) * 2 + 1];
    const float* ib = in + ((size_t)bs * C + c) * NPI + (2 * oy) * HW + 2 * ox;
    float m = -INFINITY;
#pragma unroll
    for (int dy = 0; dy < 2; dy++)
#pragma unroll
        for (int dx = 0; dx < 2; dx++) {
            float v = ib[dy * HW + dx];
            if (RELU) v = fmaxf(v, 0.f);
            v = fmaf(v, scl, sh);
            m = fmaxf(m, v);
        }
    out[idx] = m;
    if (EMB) {
        int b = bs >> 2;
        emb[(((size_t)b * C + c) * 4 + s) * NPO + p] = m;
    }
}

// ---------------- fused implicit-GEMM conv (single buffer + register A-prefetch) ----------------
// out[MROWS x NPIX] = W[MROWS x CIN*9] @ patches(in)^T + bias
template<int MROWS, int WROWS, int MA, int CIN, int HW, int NPIX, bool NORM>
__global__ void __launch_bounds__(WROWS * 128) cgemm(
    const __nv_bfloat16* __restrict__ Whi, const __nv_bfloat16* __restrict__ Wlo,
    const float* __restrict__ bias, const float* __restrict__ in,
    const float* __restrict__ stats, float* __restrict__ out)
{
    constexpr int KK      = CIN * 9;
    constexpr int NCH     = KK / 32;
    constexpr int MTILE   = WROWS * MA * 16;
    constexpr int THREADS = WROWS * 128;
    constexpr int STR     = 40;
    constexpr int NPREF   = (MTILE * 8) / THREADS;   // uint4 per thread (4 or 3)
    constexpr int TROWS   = 128 / HW;
    constexpr int PADW    = HW + 2;
    constexpr int ROWS    = TROWS + 2;
    constexpr int PLANE   = ROWS * PADW;
    constexpr int NP      = HW * HW;

    extern __shared__ char dsm[];
    uint32_t*      s_img = (uint32_t*)dsm;                          // CIN*PLANE packed
    __nv_bfloat16* sA    = (__nv_bfloat16*)(dsm + CIN * PLANE * 4); // [2 arr][MTILE][STR]
    __nv_bfloat16* sB    = sA + 2 * MTILE * STR;                    // [2 arr][128][STR]

    const int tid  = threadIdx.x;
    const int warp = tid >> 5, lane = tid & 31;
    const int wm = warp >> 2, wn = warp & 3;
    const int bs = blockIdx.y;
    const int s  = bs & 3;
    const int nt = blockIdx.x;
    const int n0 = nt * 128, y0 = nt * TROWS;
    const int g  = lane >> 2, tg = lane & 3;

    // stage padded image region, packed (hi|lo)
    const float* inb = in + (size_t)bs * CIN * NP;
    for (int i = tid; i < CIN * PLANE; i += THREADS) {
        int ci = i / PLANE, r = i - ci * PLANE;
        int ry = r / PADW, rx = r - ry * PADW;
        int gy = y0 + ry - 1, gx = rx - 1;
        uint32_t pk = 0;
        if (gy >= 0 && gy < HW && gx >= 0 && gx < HW) {
            float v = inb[(size_t)ci * NP + gy * HW + gx];
            if (NORM)
                v = fmaf(v, stats[(s * CIN + ci) * 2], stats[(s * CIN + ci) * 2 + 1]);
            pk = split_pack(v);
        }
        s_img[i] = pk;
    }

    float acc[MA][4][4] = {};
    uint4 pref[NPREF];

    const uint32_t baseA0 = smem_u32(sA);
    const uint32_t baseA1 = smem_u32(sA + MTILE * STR);
    const uint32_t baseB0 = smem_u32(sB);
    const uint32_t baseB1 = smem_u32(sB + 128 * STR);
    const int arowA = wm * (MA * 16) + (lane & 15);
    const int acolA = (lane >> 4) * 8;
    const int browB = wn * 32 + (lane & 7) + ((lane >> 4) & 1) * 8;
    const int bcolB = ((lane >> 3) & 1) * 8;

    auto prefA = [&](int kc) {
#pragma unroll
        for (int j = 0; j < NPREF; j++) {
            int i = tid + j * THREADS;
            int arr = i / (MTILE * 4);
            int r   = (i >> 2) % MTILE;
            int seg = i & 3;
            pref[j] = *(const uint4*)((arr ? Wlo : Whi) + (size_t)r * KK + kc * 32 + seg * 8);
        }
    };
    auto storeA = [&]() {
#pragma unroll
        for (int j = 0; j < NPREF; j++) {
            int i = tid + j * THREADS;
            int arr = i / (MTILE * 4);
            int r   = (i >> 2) % MTILE;
            int seg = i & 3;
            *(uint4*)&sA[(arr * MTILE + r) * STR + seg * 8] = pref[j];
        }
    };
    auto buildB = [&](int kc) {
        for (int i = tid; i < 4096; i += THREADS) {
            int n = i >> 5, kloc = i & 31;
            int k  = kc * 32 + kloc;
            int ci = k / 9, tap = k - ci * 9;
            int dy = tap / 3, dx = tap - dy * 3;
            int yl = n / HW, xl = n - yl * HW;
            uint32_t pk = s_img[ci * PLANE + (yl + dy) * PADW + (xl + dx)];
            ((uint16_t*)sB)[n * STR + kloc]         = (uint16_t)(pk & 0xFFFF);
            ((uint16_t*)sB)[(128 + n) * STR + kloc] = (uint16_t)(pk >> 16);
        }
    };

    prefA(0);                  // LDGs in flight during s_img sync
    __syncthreads();           // s_img ready
    storeA();
    buildB(0);
    __syncthreads();

    for (int kc = 0; kc < NCH; kc++) {
        if (kc + 1 < NCH) prefA(kc + 1);   // gmem loads overlap MMA below
#pragma unroll
        for (int ks = 0; ks < 2; ks++) {
            uint32_t a[2][MA][4];
#pragma unroll
            for (int ma = 0; ma < MA; ma++) {
                ldsm4(a[0][ma], baseA0 + (uint32_t)((arowA + ma * 16) * STR + ks * 16 + acolA) * 2);
                ldsm4(a[1][ma], baseA1 + (uint32_t)((arowA + ma * 16) * STR + ks * 16 + acolA) * 2);
            }
            uint32_t b[2][2][4];
#pragma unroll
            for (int np = 0; np < 2; np++) {
                ldsm4(b[0][np], baseB0 + (uint32_t)((browB + np * 16) * STR + ks * 16 + bcolB) * 2);
                ldsm4(b[1][np], baseB1 + (uint32_t)((browB + np * 16) * STR + ks * 16 + bcolB) * 2);
            }
#pragma unroll
            for (int ma = 0; ma < MA; ma++)
#pragma unroll
                for (int na = 0; na < 4; na++) {
                    int np = na >> 1, sub = na & 1;
                    uint32_t bh0 = b[0][np][sub * 2], bh1 = b[0][np][sub * 2 + 1];
                    uint32_t bl0 = b[1][np][sub * 2], bl1 = b[1][np][sub * 2 + 1];
                    mma16816(acc[ma][na], a[0][ma], bh0, bh1);
                    mma16816(acc[ma][na], a[0][ma], bl0, bl1);
                    mma16816(acc[ma][na], a[1][ma], bh0, bh1);
                }
        }
        if (kc + 1 < NCH) {
            __syncthreads();   // chunk kc fully consumed by all warps
            storeA();
            buildB(kc + 1);
            __syncthreads();
        }
    }

    // epilogue
#pragma unroll
    for (int ma = 0; ma < MA; ma++) {
        int mA = wm * (MA * 16) + ma * 16 + g;
        int mB = mA + 8;
        float bvA = bias[mA], bvB = bias[mB];
        float* orA = out + ((size_t)bs * MROWS + mA) * NPIX + n0 + wn * 32;
        float* orB = out + ((size_t)bs * MROWS + mB) * NPIX + n0 + wn * 32;
#pragma unroll
        for (int na = 0; na < 4; na++) {
            int nc = na * 8 + 2 * tg;
            *(float2*)(orA + nc) = make_float2(acc[ma][na][0] + bvA, acc[ma][na][1] + bvA);
            *(float2*)(orB + nc) = make_float2(acc[ma][na][2] + bvB, acc[ma][na][3] + bvB);
        }
    }
}

// ---------------- deformable sampling -> K-major bf16 hi/lo patches ----------------
template<int HW>
__global__ void __launch_bounds__(256) dsample_tc(
    const float* __restrict__ in, const float* __restrict__ off,
    __nv_bfloat16* __restrict__ Phi, __nv_bfloat16* __restrict__ Plo)
{
    constexpr int NP = HW * HW;
    constexpr int NCHK = NP / 256;
    extern __shared__ float sdyn[];
    float* s_img = sdyn;
    uint32_t* s_tr = (uint32_t*)(sdyn + 16 * NP);
    const int g  = blockIdx.x;
    const int bs = blockIdx.y;
    const int tid = threadIdx.x;
    const float* inb = in + ((size_t)bs * 128 + g * 16) * NP;
    for (int i = tid; i < 16 * NP; i += 256) s_img[i] = inb[i];
    __syncthreads();
    const float* offb = off + ((size_t)bs * 144 + g * 18) * NP;
    uint32_t* Ph32 = (uint32_t*)Phi;
    uint32_t* Pl32 = (uint32_t*)Plo;
    const size_t imgbase = (size_t)bs * NP * 1152;

    for (int chunk = 0; chunk < NCHK; chunk++) {
        int p = chunk * 256 + tid;
        int y = p / HW, x = p % HW;
#pragma unroll
        for (int k = 0; k < 9; k++) {
            float py = (float)(y + (k / 3) - 1) + offb[(size_t)(2 * k) * NP + p];
            float px = (float)(x + (k % 3) - 1) + offb[(size_t)(2 * k + 1) * NP + p];
            float fy = floorf(py), fx = floorf(px);
            float ly = py - fy, lx = px - fx;
            int y0 = (int)fy, x0 = (int)fx;
            int y1 = y0 + 1,  x1 = x0 + 1;
            float vy0 = (y0 >= 0 && y0 < HW) ? 1.f : 0.f;
            float vy1 = (y1 >= 0 && y1 < HW) ? 1.f : 0.f;
            float vx0 = (x0 >= 0 && x0 < HW) ? 1.f : 0.f;
            float vx1 = (x1 >= 0 && x1 < HW) ? 1.f : 0.f;
            int yc0 = min(max(y0, 0), HW - 1), yc1 = min(max(y1, 0), HW - 1);
            int xc0 = min(max(x0, 0), HW - 1), xc1 = min(max(x1, 0), HW - 1);
            float w00 = (1.f - ly) * (1.f - lx) * vy0 * vx0;
            float w01 = (1.f - ly) * lx         * vy0 * vx1;
            float w10 = ly         * (1.f - lx) * vy1 * vx0;
            float w11 = ly         * lx         * vy1 * vx1;
            int i00 = yc0 * HW + xc0, i01 = yc0 * HW + xc1;
            int i10 = yc1 * HW + xc0, i11 = yc1 * HW + xc1;
#pragma unroll
            for (int cp = 0; cp < 16; cp++) {
                const float* pl = s_img + cp * NP;
                float v = w00 * pl[i00] + w01 * pl[i01] + w10 * pl[i10] + w11 * pl[i11];
                s_tr[tid * 144 + cp * 9 + k] = split_pack(v);
            }
        }
        __syncthreads();
        for (int idx = tid; idx < 256 * 72; idx += 256) {
            int row = idx / 72, j = idx % 72;
            uint32_t a  = s_tr[row * 144 + 2 * j];
            uint32_t b2 = s_tr[row * 144 + 2 * j + 1];
            uint32_t hp = __byte_perm(a, b2, 0x5410);
            uint32_t lp = __byte_perm(a, b2, 0x7632);
            size_t o = imgbase + (size_t)(chunk * 256 + row) * 1152 + g * 144 + 2 * j;
            Ph32[o >> 1] = hp;
            Pl32[o >> 1] = lp;
        }
        __syncthreads();
    }
}

// ---------------- warp-MMA bf16-split GEMM (deform; R11-proven 2-sync version) ----------------
template<int MROWS, int KK, int NPIX>
__global__ void __launch_bounds__(256) gemm_mma(
    const __nv_bfloat16* __restrict__ Whi, const __nv_bfloat16* __restrict__ Wlo,
    const float* __restrict__ bias,
    const __nv_bfloat16* __restrict__ Phi, const __nv_bfloat16* __restrict__ Plo,
    float* __restrict__ out)
{
    constexpr int MT  = MROWS / 128;
    constexpr int STR = 40;

    __shared__ __align__(16) __nv_bfloat16 sA[2][128][STR];
    __shared__ __align__(16) __nv_bfloat16 sB[2][128][STR];

    const int tid  = threadIdx.x;
    const int warp = tid >> 5, lane = tid & 31;
    const int wm = warp >> 2, wn = warp & 3;
    const int bs = blockIdx.y;
    const int mt = blockIdx.x % MT, nt = blockIdx.x / MT;
    const int m0 = mt * 128, n0 = nt * 128;
    const int g  = lane >> 2, tg = lane & 3;

    float acc[4][4][4] = {};

    const uint32_t baseA[2] = { smem_u32(&sA[0][0][0]), smem_u32(&sA[1][0][0]) };
    const uint32_t baseB[2] = { smem_u32(&sB[0][0][0]), smem_u32(&sB[1][0][0]) };
    const int arowA = wm * 64 + (lane & 15);
    const int acolA = (lane >> 4) * 8;
    const int browB = wn * 32 + (lane & 7) + ((lane >> 4) & 1) * 8;
    const int bcolB = ((lane >> 3) & 1) * 8;

    const size_t prow = (size_t)bs * NPIX + n0;

    for (int kc = 0; kc < KK / 32; kc++) {
        __syncthreads();
        for (int i = tid; i < 2048; i += 256) {
            int half = i >> 10;          // 0: A, 1: B
            int arr  = (i >> 9) & 1;
            int r    = (i >> 2) & 127;
            int seg  = i & 3;
            if (half == 0) {
                const __nv_bfloat16* src =
                    (arr ? Wlo : Whi) + (size_t)(m0 + r) * KK + kc * 32 + seg * 8;
                *(uint4*)&sA[arr][r][seg * 8] = *(const uint4*)src;
            } else {
                const __nv_bfloat16* src =
                    (arr ? Plo : Phi) + (prow + r) * KK + kc * 32 + seg * 8;
                *(uint4*)&sB[arr][r][seg * 8] = *(const uint4*)src;
            }
        }
        __syncthreads();

#pragma unroll
        for (int ks = 0; ks < 2; ks++) {
            uint32_t a[2][4][4];
#pragma unroll
            for (int h = 0; h < 2; h++)
#pragma unroll
                for (int ma = 0; ma < 4; ma++)
                    ldsm4(a[h][ma],
                          baseA[h] + (uint32_t)((arowA + ma * 16) * STR + ks * 16 + acolA) * 2);
            uint32_t b[2][2][4];
#pragma unroll
            for (int h = 0; h < 2; h++)
#pragma unroll
                for (int np = 0; np < 2; np++)
                    ldsm4(b[h][np],
                          baseB[h] + (uint32_t)((browB + np * 16) * STR + ks * 16 + bcolB) * 2);
#pragma unroll
            for (int ma = 0; ma < 4; ma++)
#pragma unroll
                for (int na = 0; na < 4; na++) {
                    int np = na >> 1, sub = na & 1;
                    uint32_t bh0 = b[0][np][sub * 2], bh1 = b[0][np][sub * 2 + 1];
                    uint32_t bl0 = b[1][np][sub * 2], bl1 = b[1][np][sub * 2 + 1];
                    mma16816(acc[ma][na], a[0][ma], bh0, bh1);
                    mma16816(acc[ma][na], a[0][ma], bl0, bl1);
                    mma16816(acc[ma][na], a[1][ma], bh0, bh1);
                }
        }
    }

#pragma unroll
    for (int ma = 0; ma < 4; ma++) {
        int mA = m0 + wm * 64 + ma * 16 + g;
        int mB = mA + 8;
        float bvA = bias[mA], bvB = bias[mB];
        float* orA = out + ((size_t)bs * MROWS + mA) * NPIX + n0 + wn * 32;
        float* orB = out + ((size_t)bs * MROWS + mB) * NPIX + n0 + wn * 32;
#pragma unroll
        for (int na = 0; na < 4; na++) {
            int nc = na * 8 + 2 * tg;
            *(float2*)(orA + nc) = make_float2(acc[ma][na][0] + bvA, acc[ma][na][1] + bvA);
            *(float2*)(orB + nc) = make_float2(acc[ma][na][2] + bvB, acc[ma][na][3] + bvB);
        }
    }
}

// ---------------- strength (relu of max over s) + FC -> logits ----------------
__global__ void __launch_bounds__(256) fc_kernel(
    const float* __restrict__ t6, const float* __restrict__ wfc,
    const float* __restrict__ bfc, float* __restrict__ out)
{
    const int b = blockIdx.x;
    float acc[10];
#pragma unroll
    for (int j = 0; j < 10; j++) acc[j] = 0.f;
    const float* tb0 = t6 + (size_t)b * 4 * 16384;
    for (int i = threadIdx.x; i < 16384; i += 256) {
        float m = tb0[i];
        m = fmaxf(m, tb0[i + 16384]);
        m = fmaxf(m, tb0[i + 2 * 16384]);
        m = fmaxf(m, tb0[i + 3 * 16384]);
        m = fmaxf(m, 0.f);
#pragma unroll
        for (int j = 0; j < 10; j++)
            acc[j] = fmaf(m, wfc[(size_t)j * 16384 + i], acc[j]);
    }
    __shared__ float red[256];
    for (int j = 0; j < 10; j++) {
        red[threadIdx.x] = acc[j];
        __syncthreads();
        for (int st = 128; st > 0; st >>= 1) {
            if (threadIdx.x < st) red[threadIdx.x] += red[threadIdx.x + st];
            __syncthreads();
        }
        if (threadIdx.x == 0) out[b * 10 + j] = red[0] + bfc[j];
        __syncthreads();
    }
}

// ---------------- launch ----------------
extern "C" void kernel_launch(void* const* d_in, const int* in_sizes, int n_in,
                              void* d_out, int out_size) {
    const float* x   = (const float*)d_in[0];
    const float* w1  = (const float*)d_in[1];
    const float* b1  = (const float*)d_in[2];
    const float* g1  = (const float*)d_in[3];
    const float* be1 = (const float*)d_in[4];
    const float* w2  = (const float*)d_in[5];
    const float* b2  = (const float*)d_in[6];
    const float* wo1 = (const float*)d_in[7];
    const float* bo1 = (const float*)d_in[8];
    const float* wd1 = (const float*)d_in[9];
    const float* bd1 = (const float*)d_in[10];
    const float* g2  = (const float*)d_in[11];
    const float* be2 = (const float*)d_in[12];
    const float* wo2 = (const float*)d_in[13];
    const float* bo2 = (const float*)d_in[14];
    const float* wd2 = (const float*)d_in[15];
    const float* bd2 = (const float*)d_in[16];
    const float* g3  = (const float*)d_in[17];
    const float* be3 = (const float*)d_in[18];
    const float* wfc = (const float*)d_in[19];
    const float* bfc = (const float*)d_in[20];
    float* out = (float*)d_out;

    float *t1, *st1, *t2, *off1, *t3, *st2, *t4, *off2, *t5, *st3, *t6;
    __nv_bfloat16 *P1h, *P1l, *P2h, *P2l;
    __nv_bfloat16 *w1h, *w1l, *w2h, *w2l, *wc2h, *wc2l, *wo1h, *wo1l, *wo2h, *wo2l;
    cudaGetSymbolAddress((void**)&t1,   g_t1);
    cudaGetSymbolAddress((void**)&st1,  g_st1);
    cudaGetSymbolAddress((void**)&t2,   g_t2);
    cudaGetSymbolAddress((void**)&off1, g_off1);
    cudaGetSymbolAddress((void**)&P1h,  g_P1h);
    cudaGetSymbolAddress((void**)&P1l,  g_P1l);
    cudaGetSymbolAddress((void**)&t3,   g_t3);
    cudaGetSymbolAddress((void**)&st2,  g_st2);
    cudaGetSymbolAddress((void**)&t4,   g_t4);
    cudaGetSymbolAddress((void**)&off2, g_off2);
    cudaGetSymbolAddress((void**)&P2h,  g_P2h);
    cudaGetSymbolAddress((void**)&P2l,  g_P2l);
    cudaGetSymbolAddress((void**)&t5,   g_t5);
    cudaGetSymbolAddress((void**)&st3,  g_st3);
    cudaGetSymbolAddress((void**)&t6,   g_t6);
    cudaGetSymbolAddress((void**)&w1h,  g_w1h);
    cudaGetSymbolAddress((void**)&w1l,  g_w1l);
    cudaGetSymbolAddress((void**)&w2h,  g_w2h);
    cudaGetSymbolAddress((void**)&w2l,  g_w2l);
    cudaGetSymbolAddress((void**)&wc2h, g_wc2h);
    cudaGetSymbolAddress((void**)&wc2l, g_wc2l);
    cudaGetSymbolAddress((void**)&wo1h, g_wo1h);
    cudaGetSymbolAddress((void**)&wo1l, g_wo1l);
    cudaGetSymbolAddress((void**)&wo2h, g_wo2h);
    cudaGetSymbolAddress((void**)&wo2l, g_wo2l);

    cudaFuncSetAttribute(dsample_tc<32>, cudaFuncAttributeMaxDynamicSharedMemorySize, 212992);
    cudaFuncSetAttribute(dsample_tc<16>, cudaFuncAttributeMaxDynamicSharedMemorySize, 163840);
    // cgemm smem: s_img + A + B (single buffers, R11 sizes)
    cudaFuncSetAttribute((const void*)cgemm<128, 2, 4, 64, 32, 1024, true>,
                         cudaFuncAttributeMaxDynamicSharedMemorySize, 52224 + 20480 + 20480);
    cudaFuncSetAttribute((const void*)cgemm<144, 3, 3, 128, 32, 1024, false>,
                         cudaFuncAttributeMaxDynamicSharedMemorySize, 104448 + 23040 + 20480);
    cudaFuncSetAttribute((const void*)cgemm<144, 3, 3, 128, 16, 256, false>,
                         cudaFuncAttributeMaxDynamicSharedMemorySize, 92160 + 23040 + 20480);

    // 1: all weight splits (one launch)
    wconv_all<<<(847872 + 255) / 256, 256>>>(wd1, wd2, w2, wo1, wo2);
    // 2: conv1 + relu (FFMA2, reads x in packed layout directly)
    conv3x3_v2<3, 64, 32, 3, 512, true><<<dim3(4, 64), 512>>>(x, w1, b1, t1);
    // 3: BN1 stats
    bnstats_kernel<64, 1024, false, false><<<256, 256>>>(t1, g1, be1, st1);
    // 4: conv2 fused implicit-GEMM (BN1 folded at staging)  <- profiled launch
    cgemm<128, 2, 4, 64, 32, 1024, true><<<dim3(8, 64), 256, 93184>>>(
        wc2h, wc2l, b2, t1, st1, t2);
    // 5: offset conv 1 fused
    cgemm<144, 3, 3, 128, 32, 1024, false><<<dim3(8, 64), 384, 147968>>>(
        wo1h, wo1l, bo1, t2, nullptr, off1);
    // deform 1: sample + GEMM
    dsample_tc<32><<<dim3(8, 64), 256, 212992>>>(t2, off1, P1h, P1l);
    gemm_mma<128, 1152, 1024><<<dim3(8, 64), 256>>>(w1h, w1l, bd1, P1h, P1l, t3);
    // relu + BN2 + maxpool
    bnstats_kernel<128, 1024, true, true><<<512, 256>>>(t3, g2, be2, st2);
    bnpool_kernel<128, 32, true, false><<<(64 * 128 * 256) / 256, 256>>>(t3, st2, t4, nullptr);
    // offset conv 2 fused
    cgemm<144, 3, 3, 128, 16, 256, false><<<dim3(2, 64), 384, 135680>>>(
        wo2h, wo2l, bo2, t4, nullptr, off2);
    // deform 2: sample + GEMM
    dsample_tc<16><<<dim3(8, 64), 256, 163840>>>(t4, off2, P2h, P2l);
    gemm_mma<256, 1152, 256><<<dim3(4, 64), 256>>>(w2h, w2l, bd2, P2h, P2l, t5);
    // BN3 + maxpool, write embedding to out[160:]
    bnstats_kernel<256, 256, false, true><<<1024, 256>>>(t5, g3, be3, st3);
    bnpool_kernel<256, 16, false, true><<<(64 * 256 * 64) / 256, 256>>>(t5, st3, t6, out + 160);
    // logits to out[0:160]
    fc_kernel<<<16, 256>>>(t6, wfc, bfc, out);
}

// round 15
// speedup vs baseline: 1.7226x; 1.0501x over previous
#include <cuda_runtime.h>
#include <cuda_bf16.h>
#include <math.h>
#include <stdint.h>

// Problem constants: B=16, N=64, S=4, H=W=32, DG=8, K=9, EPS=1e-5.  BS = 64 images.
#define EPSV 1e-5f

// ---------------- scratch ----------------
__device__ float g_t1  [64 * 64  * 1024];
__device__ float g_st1 [4 * 64 * 2];
__device__ float g_t2  [64 * 128 * 1024];
__device__ float g_off1[64 * 144 * 1024];
__device__ __nv_bfloat16 g_P1h[(size_t)64 * 1024 * 1152];   // deform1 patches
__device__ __nv_bfloat16 g_P1l[(size_t)64 * 1024 * 1152];
__device__ float g_t3  [64 * 128 * 1024];
__device__ float g_st2 [4 * 128 * 2];
__device__ float g_t4  [64 * 128 * 256];
__device__ float g_off2[64 * 144 * 256];
__device__ __nv_bfloat16 g_P2h[(size_t)64 * 256 * 1152];    // deform2 patches
__device__ __nv_bfloat16 g_P2l[(size_t)64 * 256 * 1152];
__device__ float g_t5  [64 * 256 * 256];
__device__ float g_st3 [4 * 256 * 2];
__device__ float g_t6  [64 * 256 * 64];
__device__ __nv_bfloat16 g_w1h [128 * 1152], g_w1l [128 * 1152];   // wd1
__device__ __nv_bfloat16 g_w2h [256 * 1152], g_w2l [256 * 1152];   // wd2
__device__ __nv_bfloat16 g_wc2h[128 * 576],  g_wc2l[128 * 576];    // w2 (conv2)
__device__ __nv_bfloat16 g_wo1h[144 * 1152], g_wo1l[144 * 1152];   // wo1
__device__ __nv_bfloat16 g_wo2h[144 * 1152], g_wo2l[144 * 1152];   // wo2

// ---------------- helpers ----------------
__device__ __forceinline__ uint32_t smem_u32(const void* p) {
    uint32_t a;
    asm("{ .reg .u64 t; cvta.to.shared.u64 t, %1; cvt.u32.u64 %0, t; }" : "=r"(a) : "l"(p));
    return a;
}
__device__ __forceinline__ void ldsm4(uint32_t* r, uint32_t addr) {
    asm volatile("ldmatrix.sync.aligned.m8n8.x4.shared.b16 {%0,%1,%2,%3}, [%4];"
                 : "=r"(r[0]), "=r"(r[1]), "=r"(r[2]), "=r"(r[3]) : "r"(addr));
}
__device__ __forceinline__ void mma16816(float* c, const uint32_t* a, uint32_t b0, uint32_t b1) {
    asm volatile("mma.sync.aligned.m16n8k16.row.col.f32.bf16.bf16.f32 "
                 "{%0,%1,%2,%3}, {%4,%5,%6,%7}, {%8,%9}, {%0,%1,%2,%3};"
                 : "+f"(c[0]), "+f"(c[1]), "+f"(c[2]), "+f"(c[3])
                 : "r"(a[0]), "r"(a[1]), "r"(a[2]), "r"(a[3]), "r"(b0), "r"(b1));
}
__device__ __forceinline__ uint32_t split_pack(float v) {
    __nv_bfloat16 h = __float2bfloat16(v);
    float r = v - __bfloat162float(h);
    __nv_bfloat16 l = __float2bfloat16(r);
    return (uint32_t)__bfloat16_as_ushort(h) | ((uint32_t)__bfloat16_as_ushort(l) << 16);
}

// ---------------- f32x2 helpers (conv1 only) ----------------
__device__ __forceinline__ unsigned long long pack2(float lo, float hi) {
    unsigned long long r;
    asm("mov.b64 %0, {%1, %2};" : "=l"(r) : "f"(lo), "f"(hi));
    return r;
}
__device__ __forceinline__ void unpack2(unsigned long long v, float& lo, float& hi) {
    asm("mov.b64 {%0, %1}, %2;" : "=f"(lo), "=f"(hi) : "l"(v));
}
__device__ __forceinline__ void ffma2(unsigned long long& d,
                                      unsigned long long a, unsigned long long b) {
    asm("fma.rn.f32x2 %0, %1, %2, %0;" : "+l"(d) : "l"(a), "l"(b));
}

// ---------------- all weight bf16 splits in one launch ----------------
__global__ void wconv_all(const float* wd1, const float* wd2, const float* w2,
                          const float* wo1, const float* wo2) {
    int i = blockIdx.x * 256 + threadIdx.x;
    const float* src; __nv_bfloat16 *hi, *lo; int base;
    if      (i < 147456)  { src = wd1; hi = g_w1h;  lo = g_w1l;  base = 0; }
    else if (i < 442368)  { src = wd2; hi = g_w2h;  lo = g_w2l;  base = 147456; }
    else if (i < 516096)  { src = w2;  hi = g_wc2h; lo = g_wc2l; base = 442368; }
    else if (i < 681984)  { src = wo1; hi = g_wo1h; lo = g_wo1l; base = 516096; }
    else if (i < 847872)  { src = wo2; hi = g_wo2h; lo = g_wo2l; base = 681984; }
    else return;
    int j = i - base;
    float v = src[j];
    __nv_bfloat16 h = __float2bfloat16(v);
    hi[j] = h;
    lo[j] = __float2bfloat16(v - __bfloat162float(h));
}

// ---------------- direct 3x3 conv (oc-paired f32x2) — conv1 only ----------------
template<int CIN, int COUT, int HW, int CHUNK, int BLKT, bool RELU>
__global__ void __launch_bounds__(BLKT) conv3x3_v2(
    const float* __restrict__ in, const float* __restrict__ wt,
    const float* __restrict__ bias, float* __restrict__ out)
{
    constexpr int NP    = HW * HW;
    constexpr int P     = NP / BLKT;
    constexpr int PLW   = HW + 2;
    constexpr int PLANE = PLW * PLW;

    __shared__ __align__(16) float  s_in[CHUNK * PLANE];
    __shared__ __align__(16) float2 s_w2[CHUNK * 8 * 9];

    const int bs  = blockIdx.y;
    const int b   = bs >> 2, s = bs & 3;
    const int oc0 = blockIdx.x * 16;
    const int tid = threadIdx.x;

    unsigned long long acc2[8][P];
#pragma unroll
    for (int op = 0; op < 8; op++) {
        unsigned long long bv = pack2(bias[oc0 + 2 * op], bias[oc0 + 2 * op + 1]);
#pragma unroll
        for (int j = 0; j < P; j++) acc2[op][j] = bv;
    }

    for (int cc = 0; cc < CIN; cc += CHUNK) {
        __syncthreads();
        for (int i = tid; i < CHUNK * PLANE; i += BLKT) {
            int ci = i / PLANE, r = i - ci * PLANE;
            int y = r / PLW - 1, x = r % PLW - 1;
            float v = 0.f;
            if (y >= 0 && y < HW && x >= 0 && x < HW)
                v = in[((size_t)(b * CIN + cc + ci) * 4 + s) * NP + y * HW + x];
            s_in[i] = v;
        }
        for (int i = tid; i < CHUNK * 72; i += BLKT) {
            int ci = i / 72, r = i - ci * 72;
            int op = r / 9, t = r - op * 9;
            s_w2[i] = make_float2(
                wt[((size_t)(oc0 + 2 * op    ) * CIN + cc + ci) * 9 + t],
                wt[((size_t)(oc0 + 2 * op + 1) * CIN + cc + ci) * 9 + t]);
        }
        __syncthreads();

#pragma unroll 1
        for (int ci = 0; ci < CHUNK; ci++) {
            unsigned long long nb2[P][9];
#pragma unroll
            for (int j = 0; j < P; j++) {
                int p = tid + j * BLKT;
                const float* base = s_in + ci * PLANE + (p / HW) * PLW + (p % HW);
#pragma unroll
                for (int t = 0; t < 9; t++) {
                    float f = base[(t / 3) * PLW + (t % 3)];
                    nb2[j][t] = pack2(f, f);
                }
            }
#pragma unroll
            for (int op = 0; op < 8; op++) {
                const unsigned long long* wp =
                    (const unsigned long long*)&s_w2[(ci * 8 + op) * 9];
                unsigned long long w[9];
#pragma unroll
                for (int t = 0; t < 9; t++) w[t] = wp[t];
#pragma unroll
                for (int j = 0; j < P; j++)
#pragma unroll
                    for (int t = 0; t < 9; t++)
                        ffma2(acc2[op][j], nb2[j][t], w[t]);
            }
        }
    }

    float* ob = out + (size_t)bs * COUT * NP;
#pragma unroll
    for (int op = 0; op < 8; op++)
#pragma unroll
        for (int j = 0; j < P; j++) {
            float lo, hi;
            unpack2(acc2[op][j], lo, hi);
            if (RELU) { lo = fmaxf(lo, 0.f); hi = fmaxf(hi, 0.f); }
            int p = tid + j * BLKT;
            ob[(size_t)(oc0 + 2 * op    ) * NP + p] = lo;
            ob[(size_t)(oc0 + 2 * op + 1) * NP + p] = hi;
        }
}

// ---------------- BN stats per (s, c) ----------------
template<int C, int NP, bool RELU, bool GPS>
__global__ void __launch_bounds__(256) bnstats_kernel(
    const float* __restrict__ in, const float* __restrict__ g,
    const float* __restrict__ be, float* __restrict__ stats)
{
    const int sc_ = blockIdx.x;
    const int s = sc_ / C, c = sc_ % C;
    double sum = 0.0, sq = 0.0;
    for (int i = threadIdx.x; i < 16 * NP; i += 256) {
        int b = i / NP, p = i - b * NP;
        float v = in[((size_t)(b * 4 + s) * C + c) * NP + p];
        if (RELU) v = fmaxf(v, 0.f);
        sum += v;
        sq  += (double)v * v;
    }
    __shared__ double rs[256], rq[256];
    rs[threadIdx.x] = sum; rq[threadIdx.x] = sq;
    __syncthreads();
    for (int st = 128; st > 0; st >>= 1) {
        if (threadIdx.x < st) {
            rs[threadIdx.x] += rs[threadIdx.x + st];
            rq[threadIdx.x] += rq[threadIdx.x + st];
        }
        __syncthreads();
    }
    if (threadIdx.x == 0) {
        double cnt = 16.0 * NP;
        double m   = rs[0] / cnt;
        double var = rq[0] / cnt - m * m;
        float gg = GPS ? g[s]  : g[c];
        float bb = GPS ? be[s] : be[c];
        float scl = gg / sqrtf((float)var + EPSV);
        stats[sc_ * 2]     = scl;
        stats[sc_ * 2 + 1] = bb - (float)m * scl;
    }
}

// ---------------- BN apply + 2x2 maxpool ----------------
template<int C, int HW, bool RELU, bool EMB>
__global__ void __launch_bounds__(256) bnpool_kernel(
    const float* __restrict__ in, const float* __restrict__ stats,
    float* __restrict__ out, float* __restrict__ emb)
{
    constexpr int HO = HW / 2, NPO = HO * HO, NPI = HW * HW;
    int idx = blockIdx.x * 256 + threadIdx.x;
    if (idx >= 64 * C * NPO) return;
    int p    = idx % NPO;
    int rest = idx / NPO;
    int c  = rest % C;
    int bs = rest / C;
    int s  = bs & 3;
    int oy = p / HO, ox = p % HO;
    float scl = stats[(s * C + c) * 2];
    float sh  = stats[(s * C + c) * 2 + 1];
    const float* ib = in + ((size_t)bs * C + c) * NPI + (2 * oy) * HW + 2 * ox;
    float m = -INFINITY;
#pragma unroll
    for (int dy = 0; dy < 2; dy++)
#pragma unroll
        for (int dx = 0; dx < 2; dx++) {
            float v = ib[dy * HW + dx];
            if (RELU) v = fmaxf(v, 0.f);
            v = fmaf(v, scl, sh);
            m = fmaxf(m, v);
        }
    out[idx] = m;
    if (EMB) {
        int b = bs >> 2;
        emb[(((size_t)b * C + c) * 4 + s) * NPO + p] = m;
    }
}

// ---------------- fused implicit-GEMM conv (single buffer; optional register A-prefetch) ------
// out[MROWS x NPIX] = W[MROWS x CIN*9] @ patches(in)^T + bias
template<int MROWS, int WROWS, int MA, int CIN, int HW, int NPIX, bool NORM, bool PREF>
__global__ void __launch_bounds__(WROWS * 128) cgemm(
    const __nv_bfloat16* __restrict__ Whi, const __nv_bfloat16* __restrict__ Wlo,
    const float* __restrict__ bias, const float* __restrict__ in,
    const float* __restrict__ stats, float* __restrict__ out)
{
    constexpr int KK      = CIN * 9;
    constexpr int NCH     = KK / 32;
    constexpr int MTILE   = WROWS * MA * 16;
    constexpr int THREADS = WROWS * 128;
    constexpr int STR     = 40;
    constexpr int NPREF   = PREF ? (MTILE * 8) / THREADS : 1;
    constexpr int TROWS   = 128 / HW;
    constexpr int PADW    = HW + 2;
    constexpr int ROWS    = TROWS + 2;
    constexpr int PLANE   = ROWS * PADW;
    constexpr int NP      = HW * HW;

    extern __shared__ char dsm[];
    uint32_t*      s_img = (uint32_t*)dsm;                          // CIN*PLANE packed
    __nv_bfloat16* sA    = (__nv_bfloat16*)(dsm + CIN * PLANE * 4); // [2 arr][MTILE][STR]
    __nv_bfloat16* sB    = sA + 2 * MTILE * STR;                    // [2 arr][128][STR]

    const int tid  = threadIdx.x;
    const int warp = tid >> 5, lane = tid & 31;
    const int wm = warp >> 2, wn = warp & 3;
    const int bs = blockIdx.y;
    const int s  = bs & 3;
    const int nt = blockIdx.x;
    const int n0 = nt * 128, y0 = nt * TROWS;
    const int g  = lane >> 2, tg = lane & 3;

    // stage padded image region, packed (hi|lo)
    const float* inb = in + (size_t)bs * CIN * NP;
    for (int i = tid; i < CIN * PLANE; i += THREADS) {
        int ci = i / PLANE, r = i - ci * PLANE;
        int ry = r / PADW, rx = r - ry * PADW;
        int gy = y0 + ry - 1, gx = rx - 1;
        uint32_t pk = 0;
        if (gy >= 0 && gy < HW && gx >= 0 && gx < HW) {
            float v = inb[(size_t)ci * NP + gy * HW + gx];
            if (NORM)
                v = fmaf(v, stats[(s * CIN + ci) * 2], stats[(s * CIN + ci) * 2 + 1]);
            pk = split_pack(v);
        }
        s_img[i] = pk;
    }

    float acc[MA][4][4] = {};
    uint4 pref[NPREF];

    const uint32_t baseA0 = smem_u32(sA);
    const uint32_t baseA1 = smem_u32(sA + MTILE * STR);
    const uint32_t baseB0 = smem_u32(sB);
    const uint32_t baseB1 = smem_u32(sB + 128 * STR);
    const int arowA = wm * (MA * 16) + (lane & 15);
    const int acolA = (lane >> 4) * 8;
    const int browB = wn * 32 + (lane & 7) + ((lane >> 4) & 1) * 8;
    const int bcolB = ((lane >> 3) & 1) * 8;

    auto prefA = [&](int kc) {
#pragma unroll
        for (int j = 0; j < NPREF; j++) {
            int i = tid + j * THREADS;
            int arr = i / (MTILE * 4);
            int r   = (i >> 2) % MTILE;
            int seg = i & 3;
            pref[j] = *(const uint4*)((arr ? Wlo : Whi) + (size_t)r * KK + kc * 32 + seg * 8);
        }
    };
    auto storeA = [&]() {
#pragma unroll
        for (int j = 0; j < NPREF; j++) {
            int i = tid + j * THREADS;
            int arr = i / (MTILE * 4);
            int r   = (i >> 2) % MTILE;
            int seg = i & 3;
            *(uint4*)&sA[(arr * MTILE + r) * STR + seg * 8] = pref[j];
        }
    };
    auto stageA_direct = [&](int kc) {
        for (int i = tid; i < MTILE * 8; i += THREADS) {
            int arr = i / (MTILE * 4);
            int r   = (i >> 2) % MTILE;
            int seg = i & 3;
            const __nv_bfloat16* src =
                (arr ? Wlo : Whi) + (size_t)r * KK + kc * 32 + seg * 8;
            *(uint4*)&sA[(arr * MTILE + r) * STR + seg * 8] = *(const uint4*)src;
        }
    };
    auto buildB = [&](int kc) {
        for (int i = tid; i < 4096; i += THREADS) {
            int n = i >> 5, kloc = i & 31;
            int k  = kc * 32 + kloc;
            int ci = k / 9, tap = k - ci * 9;
            int dy = tap / 3, dx = tap - dy * 3;
            int yl = n / HW, xl = n - yl * HW;
            uint32_t pk = s_img[ci * PLANE + (yl + dy) * PADW + (xl + dx)];
            ((uint16_t*)sB)[n * STR + kloc]         = (uint16_t)(pk & 0xFFFF);
            ((uint16_t*)sB)[(128 + n) * STR + kloc] = (uint16_t)(pk >> 16);
        }
    };

    if (PREF) prefA(0);        // LDGs in flight during s_img sync
    __syncthreads();           // s_img ready
    if (PREF) storeA(); else stageA_direct(0);
    buildB(0);
    __syncthreads();

    for (int kc = 0; kc < NCH; kc++) {
        if (PREF && kc + 1 < NCH) prefA(kc + 1);   // gmem loads overlap MMA below
#pragma unroll
        for (int ks = 0; ks < 2; ks++) {
            uint32_t a[2][MA][4];
#pragma unroll
            for (int ma = 0; ma < MA; ma++) {
                ldsm4(a[0][ma], baseA0 + (uint32_t)((arowA + ma * 16) * STR + ks * 16 + acolA) * 2);
                ldsm4(a[1][ma], baseA1 + (uint32_t)((arowA + ma * 16) * STR + ks * 16 + acolA) * 2);
            }
            uint32_t b[2][2][4];
#pragma unroll
            for (int np = 0; np < 2; np++) {
                ldsm4(b[0][np], baseB0 + (uint32_t)((browB + np * 16) * STR + ks * 16 + bcolB) * 2);
                ldsm4(b[1][np], baseB1 + (uint32_t)((browB + np * 16) * STR + ks * 16 + bcolB) * 2);
            }
#pragma unroll
            for (int ma = 0; ma < MA; ma++)
#pragma unroll
                for (int na = 0; na < 4; na++) {
                    int np = na >> 1, sub = na & 1;
                    uint32_t bh0 = b[0][np][sub * 2], bh1 = b[0][np][sub * 2 + 1];
                    uint32_t bl0 = b[1][np][sub * 2], bl1 = b[1][np][sub * 2 + 1];
                    mma16816(acc[ma][na], a[0][ma], bh0, bh1);
                    mma16816(acc[ma][na], a[0][ma], bl0, bl1);
                    mma16816(acc[ma][na], a[1][ma], bh0, bh1);
                }
        }
        if (kc + 1 < NCH) {
            __syncthreads();   // chunk kc fully consumed by all warps
            if (PREF) storeA(); else stageA_direct(kc + 1);
            buildB(kc + 1);
            __syncthreads();
        }
    }

    // epilogue
#pragma unroll
    for (int ma = 0; ma < MA; ma++) {
        int mA = wm * (MA * 16) + ma * 16 + g;
        int mB = mA + 8;
        float bvA = bias[mA], bvB = bias[mB];
        float* orA = out + ((size_t)bs * MROWS + mA) * NPIX + n0 + wn * 32;
        float* orB = out + ((size_t)bs * MROWS + mB) * NPIX + n0 + wn * 32;
#pragma unroll
        for (int na = 0; na < 4; na++) {
            int nc = na * 8 + 2 * tg;
            *(float2*)(orA + nc) = make_float2(acc[ma][na][0] + bvA, acc[ma][na][1] + bvA);
            *(float2*)(orB + nc) = make_float2(acc[ma][na][2] + bvB, acc[ma][na][3] + bvB);
        }
    }
}

// ---------------- deformable sampling -> K-major bf16 hi/lo patches ----------------
template<int HW>
__global__ void __launch_bounds__(256) dsample_tc(
    const float* __restrict__ in, const float* __restrict__ off,
    __nv_bfloat16* __restrict__ Phi, __nv_bfloat16* __restrict__ Plo)
{
    constexpr int NP = HW * HW;
    constexpr int NCHK = NP / 256;
    extern __shared__ float sdyn[];
    float* s_img = sdyn;
    uint32_t* s_tr = (uint32_t*)(sdyn + 16 * NP);
    const int g  = blockIdx.x;
    const int bs = blockIdx.y;
    const int tid = threadIdx.x;
    const float* inb = in + ((size_t)bs * 128 + g * 16) * NP;
    for (int i = tid; i < 16 * NP; i += 256) s_img[i] = inb[i];
    __syncthreads();
    const float* offb = off + ((size_t)bs * 144 + g * 18) * NP;
    uint32_t* Ph32 = (uint32_t*)Phi;
    uint32_t* Pl32 = (uint32_t*)Plo;
    const size_t imgbase = (size_t)bs * NP * 1152;

    for (int chunk = 0; chunk < NCHK; chunk++) {
        int p = chunk * 256 + tid;
        int y = p / HW, x = p % HW;
#pragma unroll
        for (int k = 0; k < 9; k++) {
            float py = (float)(y + (k / 3) - 1) + offb[(size_t)(2 * k) * NP + p];
            float px = (float)(x + (k % 3) - 1) + offb[(size_t)(2 * k + 1) * NP + p];
            float fy = floorf(py), fx = floorf(px);
            float ly = py - fy, lx = px - fx;
            int y0 = (int)fy, x0 = (int)fx;
            int y1 = y0 + 1,  x1 = x0 + 1;
            float vy0 = (y0 >= 0 && y0 < HW) ? 1.f : 0.f;
            float vy1 = (y1 >= 0 && y1 < HW) ? 1.f : 0.f;
            float vx0 = (x0 >= 0 && x0 < HW) ? 1.f : 0.f;
            float vx1 = (x1 >= 0 && x1 < HW) ? 1.f : 0.f;
            int yc0 = min(max(y0, 0), HW - 1), yc1 = min(max(y1, 0), HW - 1);
            int xc0 = min(max(x0, 0), HW - 1), xc1 = min(max(x1, 0), HW - 1);
            float w00 = (1.f - ly) * (1.f - lx) * vy0 * vx0;
            float w01 = (1.f - ly) * lx         * vy0 * vx1;
            float w10 = ly         * (1.f - lx) * vy1 * vx0;
            float w11 = ly         * lx         * vy1 * vx1;
            int i00 = yc0 * HW + xc0, i01 = yc0 * HW + xc1;
            int i10 = yc1 * HW + xc0, i11 = yc1 * HW + xc1;
#pragma unroll
            for (int cp = 0; cp < 16; cp++) {
                const float* pl = s_img + cp * NP;
                float v = w00 * pl[i00] + w01 * pl[i01] + w10 * pl[i10] + w11 * pl[i11];
                s_tr[tid * 144 + cp * 9 + k] = split_pack(v);
            }
        }
        __syncthreads();
        for (int idx = tid; idx < 256 * 72; idx += 256) {
            int row = idx / 72, j = idx % 72;
            uint32_t a  = s_tr[row * 144 + 2 * j];
            uint32_t b2 = s_tr[row * 144 + 2 * j + 1];
            uint32_t hp = __byte_perm(a, b2, 0x5410);
            uint32_t lp = __byte_perm(a, b2, 0x7632);
            size_t o = imgbase + (size_t)(chunk * 256 + row) * 1152 + g * 144 + 2 * j;
            Ph32[o >> 1] = hp;
            Pl32[o >> 1] = lp;
        }
        __syncthreads();
    }
}

// ---------------- warp-MMA bf16-split GEMM (deform; register prefetch, 2 CTA cap) ----------------
template<int MROWS, int KK, int NPIX>
__global__ void __launch_bounds__(256, 2) gemm_mma(
    const __nv_bfloat16* __restrict__ Whi, const __nv_bfloat16* __restrict__ Wlo,
    const float* __restrict__ bias,
    const __nv_bfloat16* __restrict__ Phi, const __nv_bfloat16* __restrict__ Plo,
    float* __restrict__ out)
{
    constexpr int MT  = MROWS / 128;
    constexpr int NCH = KK / 32;
    constexpr int STR = 40;

    __shared__ __align__(16) __nv_bfloat16 sA[2][128][STR];
    __shared__ __align__(16) __nv_bfloat16 sB[2][128][STR];

    const int tid  = threadIdx.x;
    const int warp = tid >> 5, lane = tid & 31;
    const int wm = warp >> 2, wn = warp & 3;
    const int bs = blockIdx.y;
    const int mt = blockIdx.x % MT, nt = blockIdx.x / MT;
    const int m0 = mt * 128, n0 = nt * 128;
    const int g  = lane >> 2, tg = lane & 3;

    float acc[4][4][4] = {};
    uint4 pref[8];

    const uint32_t baseA[2] = { smem_u32(&sA[0][0][0]), smem_u32(&sA[1][0][0]) };
    const uint32_t baseB[2] = { smem_u32(&sB[0][0][0]), smem_u32(&sB[1][0][0]) };
    const int arowA = wm * 64 + (lane & 15);
    const int acolA = (lane >> 4) * 8;
    const int browB = wn * 32 + (lane & 7) + ((lane >> 4) & 1) * 8;
    const int bcolB = ((lane >> 3) & 1) * 8;

    const size_t prow = (size_t)bs * NPIX + n0;

    auto prefAB = [&](int kc) {
#pragma unroll
        for (int j = 0; j < 8; j++) {
            int i = tid + j * 256;
            int half = i >> 10;
            int arr  = (i >> 9) & 1;
            int r    = (i >> 2) & 127;
            int seg  = i & 3;
            const __nv_bfloat16* src = (half == 0)
                ? (arr ? Wlo : Whi) + (size_t)(m0 + r) * KK + kc * 32 + seg * 8
                : (arr ? Plo : Phi) + (prow + r) * KK + kc * 32 + seg * 8;
            pref[j] = *(const uint4*)src;
        }
    };
    auto storeAB = [&]() {
#pragma unroll
        for (int j = 0; j < 8; j++) {
            int i = tid + j * 256;
            int half = i >> 10;
            int arr  = (i >> 9) & 1;
            int r    = (i >> 2) & 127;
            int seg  = i & 3;
            __nv_bfloat16* dst = (half == 0) ? &sA[arr][r][seg * 8] : &sB[arr][r][seg * 8];
            *(uint4*)dst = pref[j];
        }
    };

    prefAB(0);
    storeAB();
    __syncthreads();

    for (int kc = 0; kc < NCH; kc++) {
        if (kc + 1 < NCH) prefAB(kc + 1);   // LDGs overlap MMA below
#pragma unroll
        for (int ks = 0; ks < 2; ks++) {
            uint32_t a[2][4][4];
#pragma unroll
            for (int h = 0; h < 2; h++)
#pragma unroll
                for (int ma = 0; ma < 4; ma++)
                    ldsm4(a[h][ma],
                          baseA[h] + (uint32_t)((arowA + ma * 16) * STR + ks * 16 + acolA) * 2);
            uint32_t b[2][2][4];
#pragma unroll
            for (int h = 0; h < 2; h++)
#pragma unroll
                for (int np = 0; np < 2; np++)
                    ldsm4(b[h][np],
                          baseB[h] + (uint32_t)((browB + np * 16) * STR + ks * 16 + bcolB) * 2);
#pragma unroll
            for (int ma = 0; ma < 4; ma++)
#pragma unroll
                for (int na = 0; na < 4; na++) {
                    int np = na >> 1, sub = na & 1;
                    uint32_t bh0 = b[0][np][sub * 2], bh1 = b[0][np][sub * 2 + 1];
                    uint32_t bl0 = b[1][np][sub * 2], bl1 = b[1][np][sub * 2 + 1];
                    mma16816(acc[ma][na], a[0][ma], bh0, bh1);
                    mma16816(acc[ma][na], a[0][ma], bl0, bl1);
                    mma16816(acc[ma][na], a[1][ma], bh0, bh1);
                }
        }
        if (kc + 1 < NCH) {
            __syncthreads();   // chunk kc fully consumed
            storeAB();
            __syncthreads();
        }
    }

#pragma unroll
    for (int ma = 0; ma < 4; ma++) {
        int mA = m0 + wm * 64 + ma * 16 + g;
        int mB = mA + 8;
        float bvA = bias[mA], bvB = bias[mB];
        float* orA = out + ((size_t)bs * MROWS + mA) * NPIX + n0 + wn * 32;
        float* orB = out + ((size_t)bs * MROWS + mB) * NPIX + n0 + wn * 32;
#pragma unroll
        for (int na = 0; na < 4; na++) {
            int nc = na * 8 + 2 * tg;
            *(float2*)(orA + nc) = make_float2(acc[ma][na][0] + bvA, acc[ma][na][1] + bvA);
            *(float2*)(orB + nc) = make_float2(acc[ma][na][2] + bvB, acc[ma][na][3] + bvB);
        }
    }
}

// ---------------- strength (relu of max over s) + FC -> logits ----------------
__global__ void __launch_bounds__(256) fc_kernel(
    const float* __restrict__ t6, const float* __restrict__ wfc,
    const float* __restrict__ bfc, float* __restrict__ out)
{
    const int b = blockIdx.x;
    float acc[10];
#pragma unroll
    for (int j = 0; j < 10; j++) acc[j] = 0.f;
    const float* tb0 = t6 + (size_t)b * 4 * 16384;
    for (int i = threadIdx.x; i < 16384; i += 256) {
        float m = tb0[i];
        m = fmaxf(m, tb0[i + 16384]);
        m = fmaxf(m, tb0[i + 2 * 16384]);
        m = fmaxf(m, tb0[i + 3 * 16384]);
        m = fmaxf(m, 0.f);
#pragma unroll
        for (int j = 0; j < 10; j++)
            acc[j] = fmaf(m, wfc[(size_t)j * 16384 + i], acc[j]);
    }
    __shared__ float red[256];
    for (int j = 0; j < 10; j++) {
        red[threadIdx.x] = acc[j];
        __syncthreads();
        for (int st = 128; st > 0; st >>= 1) {
            if (threadIdx.x < st) red[threadIdx.x] += red[threadIdx.x + st];
            __syncthreads();
        }
        if (threadIdx.x == 0) out[b * 10 + j] = red[0] + bfc[j];
        __syncthreads();
    }
}

// ---------------- launch ----------------
extern "C" void kernel_launch(void* const* d_in, const int* in_sizes, int n_in,
                              void* d_out, int out_size) {
    const float* x   = (const float*)d_in[0];
    const float* w1  = (const float*)d_in[1];
    const float* b1  = (const float*)d_in[2];
    const float* g1  = (const float*)d_in[3];
    const float* be1 = (const float*)d_in[4];
    const float* w2  = (const float*)d_in[5];
    const float* b2  = (const float*)d_in[6];
    const float* wo1 = (const float*)d_in[7];
    const float* bo1 = (const float*)d_in[8];
    const float* wd1 = (const float*)d_in[9];
    const float* bd1 = (const float*)d_in[10];
    const float* g2  = (const float*)d_in[11];
    const float* be2 = (const float*)d_in[12];
    const float* wo2 = (const float*)d_in[13];
    const float* bo2 = (const float*)d_in[14];
    const float* wd2 = (const float*)d_in[15];
    const float* bd2 = (const float*)d_in[16];
    const float* g3  = (const float*)d_in[17];
    const float* be3 = (const float*)d_in[18];
    const float* wfc = (const float*)d_in[19];
    const float* bfc = (const float*)d_in[20];
    float* out = (float*)d_out;

    float *t1, *st1, *t2, *off1, *t3, *st2, *t4, *off2, *t5, *st3, *t6;
    __nv_bfloat16 *P1h, *P1l, *P2h, *P2l;
    __nv_bfloat16 *w1h, *w1l, *w2h, *w2l, *wc2h, *wc2l, *wo1h, *wo1l, *wo2h, *wo2l;
    cudaGetSymbolAddress((void**)&t1,   g_t1);
    cudaGetSymbolAddress((void**)&st1,  g_st1);
    cudaGetSymbolAddress((void**)&t2,   g_t2);
    cudaGetSymbolAddress((void**)&off1, g_off1);
    cudaGetSymbolAddress((void**)&P1h,  g_P1h);
    cudaGetSymbolAddress((void**)&P1l,  g_P1l);
    cudaGetSymbolAddress((void**)&t3,   g_t3);
    cudaGetSymbolAddress((void**)&st2,  g_st2);
    cudaGetSymbolAddress((void**)&t4,   g_t4);
    cudaGetSymbolAddress((void**)&off2, g_off2);
    cudaGetSymbolAddress((void**)&P2h,  g_P2h);
    cudaGetSymbolAddress((void**)&P2l,  g_P2l);
    cudaGetSymbolAddress((void**)&t5,   g_t5);
    cudaGetSymbolAddress((void**)&st3,  g_st3);
    cudaGetSymbolAddress((void**)&t6,   g_t6);
    cudaGetSymbolAddress((void**)&w1h,  g_w1h);
    cudaGetSymbolAddress((void**)&w1l,  g_w1l);
    cudaGetSymbolAddress((void**)&w2h,  g_w2h);
    cudaGetSymbolAddress((void**)&w2l,  g_w2l);
    cudaGetSymbolAddress((void**)&wc2h, g_wc2h);
    cudaGetSymbolAddress((void**)&wc2l, g_wc2l);
    cudaGetSymbolAddress((void**)&wo1h, g_wo1h);
    cudaGetSymbolAddress((void**)&wo1l, g_wo1l);
    cudaGetSymbolAddress((void**)&wo2h, g_wo2h);
    cudaGetSymbolAddress((void**)&wo2l, g_wo2l);

    cudaFuncSetAttribute(dsample_tc<32>, cudaFuncAttributeMaxDynamicSharedMemorySize, 212992);
    cudaFuncSetAttribute(dsample_tc<16>, cudaFuncAttributeMaxDynamicSharedMemorySize, 163840);
    // cgemm smem: s_img + A + B (single buffers)
    cudaFuncSetAttribute((const void*)cgemm<128, 2, 4, 64, 32, 1024, true, false>,
                         cudaFuncAttributeMaxDynamicSharedMemorySize, 52224 + 20480 + 20480);
    cudaFuncSetAttribute((const void*)cgemm<144, 3, 3, 128, 32, 1024, false, true>,
                         cudaFuncAttributeMaxDynamicSharedMemorySize, 104448 + 23040 + 20480);
    cudaFuncSetAttribute((const void*)cgemm<144, 3, 3, 128, 16, 256, false, true>,
                         cudaFuncAttributeMaxDynamicSharedMemorySize, 92160 + 23040 + 20480);

    // 1: all weight splits (one launch)
    wconv_all<<<(847872 + 255) / 256, 256>>>(wd1, wd2, w2, wo1, wo2);
    // 2: conv1 + relu (FFMA2, reads x in packed layout directly)
    conv3x3_v2<3, 64, 32, 3, 512, true><<<dim3(4, 64), 512>>>(x, w1, b1, t1);
    // 3: BN1 stats
    bnstats_kernel<64, 1024, false, false><<<256, 256>>>(t1, g1, be1, st1);
    // 4: conv2 fused implicit-GEMM, no prefetch (2 CTAs/SM)   <- profiled launch
    cgemm<128, 2, 4, 64, 32, 1024, true, false><<<dim3(8, 64), 256, 93184>>>(
        wc2h, wc2l, b2, t1, st1, t2);
    // 5: offset conv 1 fused, register prefetch (1 CTA by smem anyway)
    cgemm<144, 3, 3, 128, 32, 1024, false, true><<<dim3(8, 64), 384, 147968>>>(
        wo1h, wo1l, bo1, t2, nullptr, off1);
    // deform 1: sample + GEMM
    dsample_tc<32><<<dim3(8, 64), 256, 212992>>>(t2, off1, P1h, P1l);
    gemm_mma<128, 1152, 1024><<<dim3(8, 64), 256>>>(w1h, w1l, bd1, P1h, P1l, t3);
    // relu + BN2 + maxpool
    bnstats_kernel<128, 1024, true, true><<<512, 256>>>(t3, g2, be2, st2);
    bnpool_kernel<128, 32, true, false><<<(64 * 128 * 256) / 256, 256>>>(t3, st2, t4, nullptr);
    // offset conv 2 fused, register prefetch
    cgemm<144, 3, 3, 128, 16, 256, false, true><<<dim3(2, 64), 384, 135680>>>(
        wo2h, wo2l, bo2, t4, nullptr, off2);
    // deform 2: sample + GEMM
    dsample_tc<16><<<dim3(8, 64), 256, 163840>>>(t4, off2, P2h, P2l);
    gemm_mma<256, 1152, 256><<<dim3(4, 64), 256>>>(w2h, w2l, bd2, P2h, P2l, t5);
    // BN3 + maxpool, write embedding to out[160:]
    bnstats_kernel<256, 256, false, true><<<1024, 256>>>(t5, g3, be3, st3);
    bnpool_kernel<256, 16, false, true><<<(64 * 256 * 64) / 256, 256>>>(t5, st3, t6, out + 160);
    // logits to out[0:160]
    fc_kernel<<<16, 256>>>(t6, wfc, bfc, out);
}